// round 2
// baseline (speedup 1.0000x reference)
#include <cuda_runtime.h>
#include <math.h>

#define BB   2
#define SS   2048
#define HH   16
#define DD   64
#define HID  1024
#define PD   128

// ---------------- scratch (device globals — no allocation allowed) ----------------
__device__ float  g_qt[BB*HH*SS*DD];     // Q in (b,h,s,d), post-RoPE
__device__ float  g_kt[BB*HH*SS*DD];     // K in (b,h,s,d), post-RoPE
__device__ float  g_vt[BB*HH*SS*DD];     // V in (b,h,s,d)
__device__ float  g_att[BB*SS*HID];      // attention out in (b,s,h*64+d)
__device__ float  g_sp[BB*SS];           // softplus(raw)
__device__ double g_posd[BB*SS];         // fp64 cumsum positions
__device__ float  g_cos[BB*SS*32];
__device__ float  g_sin[BB*SS*32];

// ---------------- RePo MLP: h = gelu(x@W1+b1); raw = h@W2+b2; sp = softplus(raw) ----
// grid 512 blocks (8 tokens each), 128 threads (one per P-dim)
__global__ __launch_bounds__(128) void repo_mlp_kernel(
    const float* __restrict__ x, const float* __restrict__ W1,
    const float* __restrict__ b1, const float* __restrict__ W2,
    const float* __restrict__ b2)
{
    __shared__ float xs[8 * HID];
    __shared__ float red[4][8];
    int tid  = threadIdx.x;
    int row0 = blockIdx.x * 8;
    const float* xg = x + (size_t)row0 * HID;
    #pragma unroll
    for (int i = 0; i < 16; i++) {
        int lin = i * 128 + tid;
        *(float4*)&xs[lin * 4] = *(const float4*)&xg[lin * 4];
    }
    __syncthreads();

    float acc[8];
    #pragma unroll
    for (int t = 0; t < 8; t++) acc[t] = 0.f;
    int p = tid;
    for (int d = 0; d < HID; d++) {
        float w = W1[d * PD + p];
        #pragma unroll
        for (int t = 0; t < 8; t++) acc[t] = fmaf(xs[t * HID + d], w, acc[t]);
    }
    float bb = b1[p];
    float w2 = W2[p];
    float v[8];
    #pragma unroll
    for (int t = 0; t < 8; t++) {
        float z = acc[t] + bb;
        // jax.nn.gelu (approximate=True, tanh form)
        float g = 0.5f * z * (1.f + tanhf(0.7978845608028654f * (z + 0.044715f * z * z * z)));
        v[t] = g * w2;
    }
    int lane = tid & 31, warp = tid >> 5;
    #pragma unroll
    for (int t = 0; t < 8; t++) {
        float s = v[t];
        #pragma unroll
        for (int off = 16; off; off >>= 1) s += __shfl_xor_sync(0xffffffffu, s, off);
        if (lane == 0) red[warp][t] = s;
    }
    __syncthreads();
    if (tid < 8) {
        float r  = red[0][tid] + red[1][tid] + red[2][tid] + red[3][tid] + b2[0];
        // softplus = logaddexp(r, 0)
        float sp = fmaxf(r, 0.f) + log1pf(expf(-fabsf(r)));
        g_sp[row0 + tid] = sp;
    }
}

// ---------------- fp64 inclusive scan per batch (2 blocks, 1024 threads, 2 elems/thread)
__global__ __launch_bounds__(1024) void scan_kernel()
{
    __shared__ double sc[1024];
    int b = blockIdx.x, t = threadIdx.x;
    float a0 = g_sp[b * SS + 2 * t];
    float a1 = g_sp[b * SS + 2 * t + 1];
    sc[t] = (double)a0 + (double)a1;
    __syncthreads();
    for (int off = 1; off < 1024; off <<= 1) {
        double v = (t >= off) ? sc[t - off] : 0.0;
        __syncthreads();
        sc[t] += v;
        __syncthreads();
    }
    double excl = (t == 0) ? 0.0 : sc[t - 1];
    g_posd[b * SS + 2 * t]     = excl + (double)a0;
    g_posd[b * SS + 2 * t + 1] = excl + (double)a0 + (double)a1;
}

// ---------------- angles -> cos/sin (fp64 range reduction, then fast fp32 trig)
__global__ __launch_bounds__(256) void angles_kernel()
{
    int idx = blockIdx.x * 256 + threadIdx.x;     // (b*S+s)*32 + j
    int j = idx & 31, bs = idx >> 5;
    double f   = exp(((double)(-2 * j) / 64.0) * 9.210340371976184);  // 10000^(-2j/64)
    double ang = g_posd[bs] * f;
    const double twopi = 6.283185307179586476925286766559;
    ang -= floor(ang * (1.0 / twopi)) * twopi;
    float af = (float)ang;
    g_cos[idx] = cosf(af);
    g_sin[idx] = sinf(af);
}

// ---------------- QKV projections: x(4096x1024) @ W(1024x1024), store to (b,h,s,d)
// 128x128 tile, BK=8, 256 threads, 8x8 micro-tile
__global__ __launch_bounds__(256) void qkv_gemm_kernel(
    const float* __restrict__ x, const float* __restrict__ Wq,
    const float* __restrict__ Wk, const float* __restrict__ Wv)
{
    __shared__ float As[8][132];
    __shared__ float Bs[8][128];
    const float* W   = (blockIdx.z == 0) ? Wq : ((blockIdx.z == 1) ? Wk : Wv);
    float*       dst = (blockIdx.z == 0) ? g_qt : ((blockIdx.z == 1) ? g_kt : g_vt);
    int tid = threadIdx.x;
    int m0 = blockIdx.y * 128, n0 = blockIdx.x * 128;
    int tr = tid >> 4, tc = tid & 15;
    int aRow = tid >> 1, ak0 = (tid & 1) * 4;
    int bRow = tid >> 5, bn4 = (tid & 31) * 4;

    float acc[8][8];
    #pragma unroll
    for (int i = 0; i < 8; i++)
        #pragma unroll
        for (int j = 0; j < 8; j++) acc[i][j] = 0.f;

    for (int k0 = 0; k0 < HID; k0 += 8) {
        float4 av = *(const float4*)&x[(size_t)(m0 + aRow) * HID + k0 + ak0];
        As[ak0 + 0][aRow] = av.x; As[ak0 + 1][aRow] = av.y;
        As[ak0 + 2][aRow] = av.z; As[ak0 + 3][aRow] = av.w;
        *(float4*)&Bs[bRow][bn4] = *(const float4*)&W[(size_t)(k0 + bRow) * HID + n0 + bn4];
        __syncthreads();
        #pragma unroll
        for (int kk = 0; kk < 8; kk++) {
            float4 a0 = *(const float4*)&As[kk][tr * 8];
            float4 a1 = *(const float4*)&As[kk][tr * 8 + 4];
            float4 b0 = *(const float4*)&Bs[kk][tc * 8];
            float4 b1 = *(const float4*)&Bs[kk][tc * 8 + 4];
            float a[8] = {a0.x, a0.y, a0.z, a0.w, a1.x, a1.y, a1.z, a1.w};
            float b[8] = {b0.x, b0.y, b0.z, b0.w, b1.x, b1.y, b1.z, b1.w};
            #pragma unroll
            for (int i = 0; i < 8; i++)
                #pragma unroll
                for (int j = 0; j < 8; j++) acc[i][j] = fmaf(a[i], b[j], acc[i][j]);
        }
        __syncthreads();
    }
    // epilogue: transpose-store into (b,h,s,d)
    #pragma unroll
    for (int i = 0; i < 8; i++) {
        int m = m0 + tr * 8 + i;
        int b = m >> 11, s = m & 2047;
        #pragma unroll
        for (int j = 0; j < 8; j++) {
            int n = n0 + tc * 8 + j;
            int h = n >> 6, d = n & 63;
            dst[((size_t)((b * HH + h) * SS + s)) * DD + d] = acc[i][j];
        }
    }
}

// ---------------- RoPE in place on g_qt / g_kt -------------------------------------
__global__ __launch_bounds__(256) void rope_kernel()
{
    int idx = blockIdx.x * 256 + threadIdx.x;     // (((b*H+h)*S)+s)*32 + j
    int j = idx & 31;
    int s = (idx >> 5) & 2047;
    int h = (idx >> 16) & 15;
    int b = idx >> 20;
    size_t base = ((size_t)((b * HH + h) * SS + s)) * DD;
    int ci = (b * SS + s) * 32 + j;
    float c = g_cos[ci], sn = g_sin[ci];
    float q1 = g_qt[base + j], q2 = g_qt[base + 32 + j];
    g_qt[base + j]      = q1 * c - q2 * sn;
    g_qt[base + 32 + j] = q1 * sn + q2 * c;
    float k1 = g_kt[base + j], k2 = g_kt[base + 32 + j];
    g_kt[base + j]      = k1 * c - k2 * sn;
    g_kt[base + 32 + j] = k1 * sn + k2 * c;
}

// ---------------- Flash attention (fp32), BQ=64, BKV=32, full (non-causal) softmax ---
__global__ __launch_bounds__(256) void flash_kernel()
{
    __shared__ float Qs[64][65];
    __shared__ float Ks[32][65];
    __shared__ float Vs[32][65];
    __shared__ float Ps[64][33];
    int tid = threadIdx.x;
    int qt = blockIdx.x, h = blockIdx.y, b = blockIdx.z;
    const float* Qb = g_qt + ((size_t)((b * HH + h) * SS) + qt * 64) * DD;
    const float* Kb = g_kt + ((size_t)((b * HH + h) * SS)) * DD;
    const float* Vb = g_vt + ((size_t)((b * HH + h) * SS)) * DD;
    int tr = tid >> 4, tc = tid & 15;
    const float scale = 0.125f;   // 1/sqrt(64)

    #pragma unroll
    for (int i = 0; i < 4; i++) {
        int lin = i * 256 + tid;
        int r = lin >> 4, d0 = (lin & 15) * 4;
        float4 v = *(const float4*)&Qb[r * 64 + d0];
        Qs[r][d0 + 0] = v.x * scale; Qs[r][d0 + 1] = v.y * scale;
        Qs[r][d0 + 2] = v.z * scale; Qs[r][d0 + 3] = v.w * scale;
    }

    float m[4], l[4], o[4][4];
    #pragma unroll
    for (int i = 0; i < 4; i++) {
        m[i] = -INFINITY; l[i] = 0.f;
        #pragma unroll
        for (int j = 0; j < 4; j++) o[i][j] = 0.f;
    }

    for (int kv = 0; kv < SS / 32; kv++) {
        int kbase = kv * 32;
        #pragma unroll
        for (int i = 0; i < 2; i++) {
            int lin = i * 256 + tid;
            int r = lin >> 4, d0 = (lin & 15) * 4;
            float4 kvv = *(const float4*)&Kb[(size_t)(kbase + r) * 64 + d0];
            Ks[r][d0] = kvv.x; Ks[r][d0 + 1] = kvv.y; Ks[r][d0 + 2] = kvv.z; Ks[r][d0 + 3] = kvv.w;
            float4 vvv = *(const float4*)&Vb[(size_t)(kbase + r) * 64 + d0];
            Vs[r][d0] = vvv.x; Vs[r][d0 + 1] = vvv.y; Vs[r][d0 + 2] = vvv.z; Vs[r][d0 + 3] = vvv.w;
        }
        __syncthreads();

        float s[4][2];
        #pragma unroll
        for (int i = 0; i < 4; i++) { s[i][0] = 0.f; s[i][1] = 0.f; }
        #pragma unroll 16
        for (int dd = 0; dd < 64; dd++) {
            float kb0 = Ks[tc * 2 + 0][dd];
            float kb1 = Ks[tc * 2 + 1][dd];
            #pragma unroll
            for (int i = 0; i < 4; i++) {
                float qa = Qs[tr * 4 + i][dd];
                s[i][0] = fmaf(qa, kb0, s[i][0]);
                s[i][1] = fmaf(qa, kb1, s[i][1]);
            }
        }
        // online softmax (16 tc-lanes per row group share reductions via shuffle)
        #pragma unroll
        for (int i = 0; i < 4; i++) {
            float mx = fmaxf(s[i][0], s[i][1]);
            #pragma unroll
            for (int off = 8; off; off >>= 1) mx = fmaxf(mx, __shfl_xor_sync(0xffffffffu, mx, off));
            float mn    = fmaxf(m[i], mx);
            float alpha = __expf(m[i] - mn);
            float p0 = __expf(s[i][0] - mn);
            float p1 = __expf(s[i][1] - mn);
            Ps[tr * 4 + i][tc * 2 + 0] = p0;
            Ps[tr * 4 + i][tc * 2 + 1] = p1;
            float ls = p0 + p1;
            #pragma unroll
            for (int off = 8; off; off >>= 1) ls += __shfl_xor_sync(0xffffffffu, ls, off);
            l[i] = l[i] * alpha + ls;
            m[i] = mn;
            #pragma unroll
            for (int j = 0; j < 4; j++) o[i][j] *= alpha;
        }
        __syncthreads();
        #pragma unroll 8
        for (int c = 0; c < 32; c++) {
            float vv[4];
            #pragma unroll
            for (int j = 0; j < 4; j++) vv[j] = Vs[c][tc * 4 + j];
            #pragma unroll
            for (int i = 0; i < 4; i++) {
                float p = Ps[tr * 4 + i][c];
                #pragma unroll
                for (int j = 0; j < 4; j++) o[i][j] = fmaf(p, vv[j], o[i][j]);
            }
        }
        __syncthreads();
    }
    #pragma unroll
    for (int i = 0; i < 4; i++) {
        float inv = 1.f / l[i];
        int srow = qt * 64 + tr * 4 + i;
        float* outp = g_att + ((size_t)(b * SS + srow)) * HID + h * 64 + tc * 4;
        #pragma unroll
        for (int j = 0; j < 4; j++) outp[j] = o[i][j] * inv;
    }
}

// ---------------- Output projection: g_att(4096x1024) @ W_o -> d_out ----------------
__global__ __launch_bounds__(256) void oproj_gemm_kernel(
    const float* __restrict__ Wo, float* __restrict__ out)
{
    __shared__ float As[8][132];
    __shared__ float Bs[8][128];
    int tid = threadIdx.x;
    int m0 = blockIdx.y * 128, n0 = blockIdx.x * 128;
    int tr = tid >> 4, tc = tid & 15;
    int aRow = tid >> 1, ak0 = (tid & 1) * 4;
    int bRow = tid >> 5, bn4 = (tid & 31) * 4;

    float acc[8][8];
    #pragma unroll
    for (int i = 0; i < 8; i++)
        #pragma unroll
        for (int j = 0; j < 8; j++) acc[i][j] = 0.f;

    for (int k0 = 0; k0 < HID; k0 += 8) {
        float4 av = *(const float4*)&g_att[(size_t)(m0 + aRow) * HID + k0 + ak0];
        As[ak0 + 0][aRow] = av.x; As[ak0 + 1][aRow] = av.y;
        As[ak0 + 2][aRow] = av.z; As[ak0 + 3][aRow] = av.w;
        *(float4*)&Bs[bRow][bn4] = *(const float4*)&Wo[(size_t)(k0 + bRow) * HID + n0 + bn4];
        __syncthreads();
        #pragma unroll
        for (int kk = 0; kk < 8; kk++) {
            float4 a0 = *(const float4*)&As[kk][tr * 8];
            float4 a1 = *(const float4*)&As[kk][tr * 8 + 4];
            float4 b0 = *(const float4*)&Bs[kk][tc * 8];
            float4 b1 = *(const float4*)&Bs[kk][tc * 8 + 4];
            float a[8] = {a0.x, a0.y, a0.z, a0.w, a1.x, a1.y, a1.z, a1.w};
            float b[8] = {b0.x, b0.y, b0.z, b0.w, b1.x, b1.y, b1.z, b1.w};
            #pragma unroll
            for (int i = 0; i < 8; i++)
                #pragma unroll
                for (int j = 0; j < 8; j++) acc[i][j] = fmaf(a[i], b[j], acc[i][j]);
        }
        __syncthreads();
    }
    #pragma unroll
    for (int i = 0; i < 8; i++) {
        float* cp = out + (size_t)(m0 + tr * 8 + i) * HID + n0 + tc * 8;
        #pragma unroll
        for (int j = 0; j < 8; j++) cp[j] = acc[i][j];
    }
}

// ---------------- launch ------------------------------------------------------------
extern "C" void kernel_launch(void* const* d_in, const int* in_sizes, int n_in,
                              void* d_out, int out_size)
{
    const float* x  = (const float*)d_in[0];
    const float* Wq = (const float*)d_in[1];
    const float* Wk = (const float*)d_in[2];
    const float* Wv = (const float*)d_in[3];
    const float* Wo = (const float*)d_in[4];
    const float* W1 = (const float*)d_in[5];
    const float* b1 = (const float*)d_in[6];
    const float* W2 = (const float*)d_in[7];
    const float* b2 = (const float*)d_in[8];
    float* out = (float*)d_out;

    repo_mlp_kernel<<<512, 128>>>(x, W1, b1, W2, b2);
    scan_kernel<<<2, 1024>>>();
    angles_kernel<<<512, 256>>>();                 // 2*2048*32 = 131072 threads
    qkv_gemm_kernel<<<dim3(8, 32, 3), 256>>>(x, Wq, Wk, Wv);
    rope_kernel<<<8192, 256>>>();                  // 2*16*2048*32 pairs
    flash_kernel<<<dim3(32, 16, 2), 256>>>();
    oproj_gemm_kernel<<<dim3(8, 32), 256>>>(Wo, out);
}

// round 4
// speedup vs baseline: 1.3173x; 1.3173x over previous
#include <cuda_runtime.h>
#include <cuda_bf16.h>
#include <math.h>
#include <stdint.h>

#define BB   2
#define SS   2048
#define HH   16
#define DD   64
#define HID  1024
#define PD   128

// ---------------- scratch (device globals — no allocation allowed) ----------------
__device__ __align__(256) float  g_qt[BB*HH*SS*DD];     // Q (b,h,s,d) post-RoPE
__device__ __align__(256) float  g_kt[BB*HH*SS*DD];     // K (b,h,s,d) post-RoPE
__device__ __align__(256) float  g_vt[BB*HH*SS*DD];     // V (b,h,s,d)
__device__ __align__(256) float  g_att[BB*SS*HID];      // attention out (b,s,h*64+d)
__device__ float  g_sp[BB*SS];
__device__ double g_posd[BB*SS];
__device__ float  g_cos[BB*SS*32];
__device__ float  g_sin[BB*SS*32];
// bf16 hi/lo split operands for tensor-core GEMMs
__device__ __align__(256) __nv_bfloat16 g_xhi[BB*SS*HID];
__device__ __align__(256) __nv_bfloat16 g_xlo[BB*SS*HID];
__device__ __align__(256) __nv_bfloat16 g_ahi[BB*SS*HID];
__device__ __align__(256) __nv_bfloat16 g_alo[BB*SS*HID];
__device__ __align__(256) __nv_bfloat16 g_wthi[4*HID*HID];   // W^T (n,k), z = q,k,v,o
__device__ __align__(256) __nv_bfloat16 g_wtlo[4*HID*HID];

// ==================== helpers ====================
__device__ __forceinline__ uint32_t smem_u32(const void* p) {
    uint32_t a;
    asm("{ .reg .u64 t; cvta.to.shared.u64 t, %1; cvt.u32.u64 %0, t; }" : "=r"(a) : "l"(p));
    return a;
}
__device__ __forceinline__ void cp_async16(uint32_t dst, const void* src) {
    asm volatile("cp.async.cg.shared.global [%0], [%1], 16;" :: "r"(dst), "l"(src));
}
__device__ __forceinline__ void cp_commit() {
    asm volatile("cp.async.commit_group;" ::: "memory");
}
__device__ __forceinline__ void ldsm_x4(uint32_t* r, uint32_t addr) {
    asm volatile("ldmatrix.sync.aligned.m8n8.x4.shared.b16 {%0,%1,%2,%3}, [%4];"
                 : "=r"(r[0]), "=r"(r[1]), "=r"(r[2]), "=r"(r[3]) : "r"(addr));
}
__device__ __forceinline__ void mma16816(float* c, const uint32_t* a, uint32_t b0, uint32_t b1) {
    asm volatile(
        "mma.sync.aligned.m16n8k16.row.col.f32.bf16.bf16.f32 "
        "{%0,%1,%2,%3}, {%4,%5,%6,%7}, {%8,%9}, {%0,%1,%2,%3};"
        : "+f"(c[0]), "+f"(c[1]), "+f"(c[2]), "+f"(c[3])
        : "r"(a[0]), "r"(a[1]), "r"(a[2]), "r"(a[3]), "r"(b0), "r"(b1));
}

// ==================== RePo MLP ====================
__global__ __launch_bounds__(128) void repo_mlp_kernel(
    const float* __restrict__ x, const float* __restrict__ W1,
    const float* __restrict__ b1, const float* __restrict__ W2,
    const float* __restrict__ b2)
{
    __shared__ float xs[8 * HID];
    __shared__ float red[4][8];
    int tid  = threadIdx.x;
    int row0 = blockIdx.x * 8;
    const float* xg = x + (size_t)row0 * HID;
    #pragma unroll
    for (int i = 0; i < 16; i++) {
        int lin = i * 128 + tid;
        *(float4*)&xs[lin * 4] = *(const float4*)&xg[lin * 4];
    }
    __syncthreads();

    float acc[8];
    #pragma unroll
    for (int t = 0; t < 8; t++) acc[t] = 0.f;
    int p = tid;
    for (int d = 0; d < HID; d++) {
        float w = W1[d * PD + p];
        #pragma unroll
        for (int t = 0; t < 8; t++) acc[t] = fmaf(xs[t * HID + d], w, acc[t]);
    }
    float bb = b1[p];
    float w2 = W2[p];
    float v[8];
    #pragma unroll
    for (int t = 0; t < 8; t++) {
        float z = acc[t] + bb;
        float g = 0.5f * z * (1.f + tanhf(0.7978845608028654f * (z + 0.044715f * z * z * z)));
        v[t] = g * w2;
    }
    int lane = tid & 31, warp = tid >> 5;
    #pragma unroll
    for (int t = 0; t < 8; t++) {
        float s = v[t];
        #pragma unroll
        for (int off = 16; off; off >>= 1) s += __shfl_xor_sync(0xffffffffu, s, off);
        if (lane == 0) red[warp][t] = s;
    }
    __syncthreads();
    if (tid < 8) {
        float r  = red[0][tid] + red[1][tid] + red[2][tid] + red[3][tid] + b2[0];
        float sp = fmaxf(r, 0.f) + log1pf(expf(-fabsf(r)));
        g_sp[row0 + tid] = sp;
    }
}

// ==================== fp64 scan ====================
__global__ __launch_bounds__(1024) void scan_kernel()
{
    __shared__ double sc[1024];
    int b = blockIdx.x, t = threadIdx.x;
    float a0 = g_sp[b * SS + 2 * t];
    float a1 = g_sp[b * SS + 2 * t + 1];
    sc[t] = (double)a0 + (double)a1;
    __syncthreads();
    for (int off = 1; off < 1024; off <<= 1) {
        double v = (t >= off) ? sc[t - off] : 0.0;
        __syncthreads();
        sc[t] += v;
        __syncthreads();
    }
    double excl = (t == 0) ? 0.0 : sc[t - 1];
    g_posd[b * SS + 2 * t]     = excl + (double)a0;
    g_posd[b * SS + 2 * t + 1] = excl + (double)a0 + (double)a1;
}

// ==================== angles ====================
__global__ __launch_bounds__(256) void angles_kernel()
{
    int idx = blockIdx.x * 256 + threadIdx.x;
    int j = idx & 31, bs = idx >> 5;
    double f   = exp(((double)(-2 * j) / 64.0) * 9.210340371976184);
    double ang = g_posd[bs] * f;
    const double twopi = 6.283185307179586476925286766559;
    ang -= floor(ang * (1.0 / twopi)) * twopi;
    float af = (float)ang;
    g_cos[idx] = cosf(af);
    g_sin[idx] = sinf(af);
}

// ==================== fp32 -> bf16 hi/lo split (x or g_att) ====================
__global__ __launch_bounds__(256) void conv_split_kernel(const float* __restrict__ src_in, int use_att)
{
    const float* src = use_att ? g_att : src_in;
    __nv_bfloat16* hi = use_att ? g_ahi : g_xhi;
    __nv_bfloat16* lo = use_att ? g_alo : g_xlo;
    int idx = (blockIdx.x * 256 + threadIdx.x) * 4;
    float4 v = *(const float4*)&src[idx];
    ushort4 H, L;
    {
        __nv_bfloat16 h = __float2bfloat16(v.x); H.x = *(unsigned short*)&h;
        __nv_bfloat16 l = __float2bfloat16(v.x - __bfloat162float(h)); L.x = *(unsigned short*)&l;
    }
    {
        __nv_bfloat16 h = __float2bfloat16(v.y); H.y = *(unsigned short*)&h;
        __nv_bfloat16 l = __float2bfloat16(v.y - __bfloat162float(h)); L.y = *(unsigned short*)&l;
    }
    {
        __nv_bfloat16 h = __float2bfloat16(v.z); H.z = *(unsigned short*)&h;
        __nv_bfloat16 l = __float2bfloat16(v.z - __bfloat162float(h)); L.z = *(unsigned short*)&l;
    }
    {
        __nv_bfloat16 h = __float2bfloat16(v.w); H.w = *(unsigned short*)&h;
        __nv_bfloat16 l = __float2bfloat16(v.w - __bfloat162float(h)); L.w = *(unsigned short*)&l;
    }
    *(ushort4*)&hi[idx] = H;
    *(ushort4*)&lo[idx] = L;
}

// ==================== W (k,n) -> W^T (n,k) bf16 hi/lo ====================
__global__ void conv_wT_kernel(const float* __restrict__ Wq, const float* __restrict__ Wk,
                               const float* __restrict__ Wv, const float* __restrict__ Wo)
{
    __shared__ float t[32][33];
    int z = blockIdx.z;
    const float* W = (z == 0) ? Wq : (z == 1) ? Wk : (z == 2) ? Wv : Wo;
    int n0 = blockIdx.x * 32, k0 = blockIdx.y * 32;
    t[threadIdx.y][threadIdx.x] = W[(size_t)(k0 + threadIdx.y) * HID + n0 + threadIdx.x];
    __syncthreads();
    float v = t[threadIdx.x][threadIdx.y];   // = W[k0+tx][n0+ty]
    size_t o = ((size_t)z << 20) + (size_t)(n0 + threadIdx.y) * HID + k0 + threadIdx.x;
    __nv_bfloat16 h = __float2bfloat16(v);
    g_wthi[o] = h;
    g_wtlo[o] = __float2bfloat16(v - __bfloat162float(h));
}

// ==================== mma.sync bf16x3 GEMM: 128x128 tile, K=1024, BK=32 ====================
// smem buffer: Ahi, Alo, Bhi, Blo tiles, each 128 rows x 40 bf16 (80B padded stride)
// MODE 0: A = g_xhi/lo, B = wt[z], dst = g_qt/g_kt/g_vt ((b,h,s,d) store)
// MODE 1: A = g_ahi/lo, B = wt[3], dst = outp (row-major)
#define TILE_B   10240            // 128 * 40 * 2
#define BUF_B    (4 * TILE_B)     // 40960
#define SMEM_MM  (2 * BUF_B)      // 81920

template<int MODE>
__global__ __launch_bounds__(256) void mm_mma_kernel(float* __restrict__ outp)
{
    extern __shared__ __align__(128) char smem[];
    uint32_t sbase = smem_u32(smem);
    int tid = threadIdx.x;
    int lane = tid & 31, wid = tid >> 5;
    int wm = wid & 3, wn = wid >> 2;          // 4 m-warps x 2 n-warps

    int n0 = blockIdx.x * 128, m0 = blockIdx.y * 128;
    int z  = (MODE == 0) ? (int)blockIdx.z : 3;
    const __nv_bfloat16* Ahi = ((MODE == 0) ? g_xhi : g_ahi) + (size_t)m0 * HID;
    const __nv_bfloat16* Alo = ((MODE == 0) ? g_xlo : g_alo) + (size_t)m0 * HID;
    const __nv_bfloat16* Bhi = g_wthi + ((size_t)z << 20) + (size_t)n0 * HID;
    const __nv_bfloat16* Blo = g_wtlo + ((size_t)z << 20) + (size_t)n0 * HID;

    float acc[2][8][4];
    #pragma unroll
    for (int i = 0; i < 2; i++)
        #pragma unroll
        for (int j = 0; j < 8; j++)
            #pragma unroll
            for (int q = 0; q < 4; q++) acc[i][j][q] = 0.f;

    // ldmatrix lane address components
    int arow = lane & 15,  acg = lane >> 4;                 // A: 16 rows x 2 col-halves
    int brow = (lane & 7) + ((lane >> 4) << 3);             // B: two n8 blocks
    int bcg  = (lane >> 3) & 1;

    // prefetch chunk 0
    {
        const __nv_bfloat16* bases[4] = {Ahi, Alo, Bhi, Blo};
        #pragma unroll
        for (int it = 0; it < 8; it++) {
            int lin = it * 256 + tid;
            int tile = lin >> 9, idx = lin & 511, r = idx >> 2, cc = idx & 3;
            cp_async16(sbase + tile * TILE_B + r * 80 + cc * 16,
                       bases[tile] + (size_t)r * HID + cc * 8);
        }
        cp_commit();
    }

    for (int c = 0; c < 32; c++) {
        if (c + 1 < 32) {
            int k0 = (c + 1) * 32;
            uint32_t sb = sbase + ((c + 1) & 1) * BUF_B;
            const __nv_bfloat16* bases[4] = {Ahi, Alo, Bhi, Blo};
            #pragma unroll
            for (int it = 0; it < 8; it++) {
                int lin = it * 256 + tid;
                int tile = lin >> 9, idx = lin & 511, r = idx >> 2, cc = idx & 3;
                cp_async16(sb + tile * TILE_B + r * 80 + cc * 16,
                           bases[tile] + (size_t)r * HID + k0 + cc * 8);
            }
            cp_commit();
            asm volatile("cp.async.wait_group 1;" ::: "memory");
        } else {
            asm volatile("cp.async.wait_group 0;" ::: "memory");
        }
        __syncthreads();

        uint32_t sb   = sbase + (c & 1) * BUF_B;
        uint32_t sAhi = sb, sAlo = sb + TILE_B, sBhi = sb + 2 * TILE_B, sBlo = sb + 3 * TILE_B;

        #pragma unroll
        for (int ks = 0; ks < 2; ks++) {
            uint32_t a[2][4], bh[4][4], bl[4][4];
            // A-hi frags (2 m16 blocks)
            #pragma unroll
            for (int i = 0; i < 2; i++)
                ldsm_x4(a[i], sAhi + ((wm * 32 + i * 16 + arow) * 40 + ks * 16 + acg * 8) * 2);
            // B-hi frags (4 n16 groups = 8 n8 blocks)
            #pragma unroll
            for (int j = 0; j < 4; j++)
                ldsm_x4(bh[j], sBhi + ((wn * 64 + j * 16 + brow) * 40 + ks * 16 + bcg * 8) * 2);
            #pragma unroll
            for (int i = 0; i < 2; i++)
                #pragma unroll
                for (int j = 0; j < 8; j++)
                    mma16816(acc[i][j], a[i], bh[j >> 1][(j & 1) * 2], bh[j >> 1][(j & 1) * 2 + 1]);
            // B-lo frags, A-hi reused
            #pragma unroll
            for (int j = 0; j < 4; j++)
                ldsm_x4(bl[j], sBlo + ((wn * 64 + j * 16 + brow) * 40 + ks * 16 + bcg * 8) * 2);
            #pragma unroll
            for (int i = 0; i < 2; i++)
                #pragma unroll
                for (int j = 0; j < 8; j++)
                    mma16816(acc[i][j], a[i], bl[j >> 1][(j & 1) * 2], bl[j >> 1][(j & 1) * 2 + 1]);
            // A-lo frags, B-hi reused
            #pragma unroll
            for (int i = 0; i < 2; i++)
                ldsm_x4(a[i], sAlo + ((wm * 32 + i * 16 + arow) * 40 + ks * 16 + acg * 8) * 2);
            #pragma unroll
            for (int i = 0; i < 2; i++)
                #pragma unroll
                for (int j = 0; j < 8; j++)
                    mma16816(acc[i][j], a[i], bh[j >> 1][(j & 1) * 2], bh[j >> 1][(j & 1) * 2 + 1]);
        }
        __syncthreads();
    }

    // epilogue
    #pragma unroll
    for (int i = 0; i < 2; i++)
        #pragma unroll
        for (int j = 0; j < 8; j++) {
            int n = n0 + wn * 64 + j * 8 + (lane & 3) * 2;
            #pragma unroll
            for (int half = 0; half < 2; half++) {
                int m = m0 + wm * 32 + i * 16 + (lane >> 2) + half * 8;
                float2 val = make_float2(acc[i][j][half * 2], acc[i][j][half * 2 + 1]);
                if (MODE == 0) {
                    int b = m >> 11, s = m & 2047, h = n >> 6, d = n & 63;
                    float* dst = (z == 0) ? g_qt : (z == 1) ? g_kt : g_vt;
                    *(float2*)(dst + ((size_t)((b * HH + h) * SS + s)) * DD + d) = val;
                } else {
                    *(float2*)(outp + (size_t)m * HID + n) = val;
                }
            }
        }
}

// ==================== RoPE ====================
__global__ __launch_bounds__(256) void rope_kernel()
{
    int idx = blockIdx.x * 256 + threadIdx.x;
    int j = idx & 31;
    int s = (idx >> 5) & 2047;
    int h = (idx >> 16) & 15;
    int b = idx >> 20;
    size_t base = ((size_t)((b * HH + h) * SS + s)) * DD;
    int ci = (b * SS + s) * 32 + j;
    float c = g_cos[ci], sn = g_sin[ci];
    float q1 = g_qt[base + j], q2 = g_qt[base + 32 + j];
    g_qt[base + j]      = q1 * c - q2 * sn;
    g_qt[base + 32 + j] = q1 * sn + q2 * c;
    float k1 = g_kt[base + j], k2 = g_kt[base + 32 + j];
    g_kt[base + j]      = k1 * c - k2 * sn;
    g_kt[base + 32 + j] = k1 * sn + k2 * c;
}

// ==================== Flash attention (fp32 SIMT) ====================
__global__ __launch_bounds__(256) void flash_kernel()
{
    __shared__ float Qs[64][65];
    __shared__ float Ks[32][65];
    __shared__ float Vs[32][65];
    __shared__ float Ps[64][33];
    int tid = threadIdx.x;
    int qt = blockIdx.x, h = blockIdx.y, b = blockIdx.z;
    const float* Qb = g_qt + ((size_t)((b * HH + h) * SS) + qt * 64) * DD;
    const float* Kb = g_kt + ((size_t)((b * HH + h) * SS)) * DD;
    const float* Vb = g_vt + ((size_t)((b * HH + h) * SS)) * DD;
    int tr = tid >> 4, tc = tid & 15;
    const float scale = 0.125f;

    #pragma unroll
    for (int i = 0; i < 4; i++) {
        int lin = i * 256 + tid;
        int r = lin >> 4, d0 = (lin & 15) * 4;
        float4 v = *(const float4*)&Qb[r * 64 + d0];
        Qs[r][d0 + 0] = v.x * scale; Qs[r][d0 + 1] = v.y * scale;
        Qs[r][d0 + 2] = v.z * scale; Qs[r][d0 + 3] = v.w * scale;
    }

    float m[4], l[4], o[4][4];
    #pragma unroll
    for (int i = 0; i < 4; i++) {
        m[i] = -INFINITY; l[i] = 0.f;
        #pragma unroll
        for (int j = 0; j < 4; j++) o[i][j] = 0.f;
    }

    for (int kv = 0; kv < SS / 32; kv++) {
        int kbase = kv * 32;
        #pragma unroll
        for (int i = 0; i < 2; i++) {
            int lin = i * 256 + tid;
            int r = lin >> 4, d0 = (lin & 15) * 4;
            float4 kvv = *(const float4*)&Kb[(size_t)(kbase + r) * 64 + d0];
            Ks[r][d0] = kvv.x; Ks[r][d0 + 1] = kvv.y; Ks[r][d0 + 2] = kvv.z; Ks[r][d0 + 3] = kvv.w;
            float4 vvv = *(const float4*)&Vb[(size_t)(kbase + r) * 64 + d0];
            Vs[r][d0] = vvv.x; Vs[r][d0 + 1] = vvv.y; Vs[r][d0 + 2] = vvv.z; Vs[r][d0 + 3] = vvv.w;
        }
        __syncthreads();

        float s[4][2];
        #pragma unroll
        for (int i = 0; i < 4; i++) { s[i][0] = 0.f; s[i][1] = 0.f; }
        #pragma unroll 16
        for (int dd = 0; dd < 64; dd++) {
            float kb0 = Ks[tc * 2 + 0][dd];
            float kb1 = Ks[tc * 2 + 1][dd];
            #pragma unroll
            for (int i = 0; i < 4; i++) {
                float qa = Qs[tr * 4 + i][dd];
                s[i][0] = fmaf(qa, kb0, s[i][0]);
                s[i][1] = fmaf(qa, kb1, s[i][1]);
            }
        }
        #pragma unroll
        for (int i = 0; i < 4; i++) {
            float mx = fmaxf(s[i][0], s[i][1]);
            #pragma unroll
            for (int off = 8; off; off >>= 1) mx = fmaxf(mx, __shfl_xor_sync(0xffffffffu, mx, off));
            float mn    = fmaxf(m[i], mx);
            float alpha = __expf(m[i] - mn);
            float p0 = __expf(s[i][0] - mn);
            float p1 = __expf(s[i][1] - mn);
            Ps[tr * 4 + i][tc * 2 + 0] = p0;
            Ps[tr * 4 + i][tc * 2 + 1] = p1;
            float ls = p0 + p1;
            #pragma unroll
            for (int off = 8; off; off >>= 1) ls += __shfl_xor_sync(0xffffffffu, ls, off);
            l[i] = l[i] * alpha + ls;
            m[i] = mn;
            #pragma unroll
            for (int j = 0; j < 4; j++) o[i][j] *= alpha;
        }
        __syncthreads();
        #pragma unroll 8
        for (int c = 0; c < 32; c++) {
            float vv[4];
            #pragma unroll
            for (int j = 0; j < 4; j++) vv[j] = Vs[c][tc * 4 + j];
            #pragma unroll
            for (int i = 0; i < 4; i++) {
                float p = Ps[tr * 4 + i][c];
                #pragma unroll
                for (int j = 0; j < 4; j++) o[i][j] = fmaf(p, vv[j], o[i][j]);
            }
        }
        __syncthreads();
    }
    #pragma unroll
    for (int i = 0; i < 4; i++) {
        float inv = 1.f / l[i];
        int srow = qt * 64 + tr * 4 + i;
        float* outp = g_att + ((size_t)(b * SS + srow)) * HID + h * 64 + tc * 4;
        #pragma unroll
        for (int j = 0; j < 4; j++) outp[j] = o[i][j] * inv;
    }
}

// ==================== launch ====================
extern "C" void kernel_launch(void* const* d_in, const int* in_sizes, int n_in,
                              void* d_out, int out_size)
{
    const float* x  = (const float*)d_in[0];
    const float* Wq = (const float*)d_in[1];
    const float* Wk = (const float*)d_in[2];
    const float* Wv = (const float*)d_in[3];
    const float* Wo = (const float*)d_in[4];
    const float* W1 = (const float*)d_in[5];
    const float* b1 = (const float*)d_in[6];
    const float* W2 = (const float*)d_in[7];
    const float* b2 = (const float*)d_in[8];
    float* out = (float*)d_out;

    cudaFuncSetAttribute(mm_mma_kernel<0>, cudaFuncAttributeMaxDynamicSharedMemorySize, SMEM_MM);
    cudaFuncSetAttribute(mm_mma_kernel<1>, cudaFuncAttributeMaxDynamicSharedMemorySize, SMEM_MM);

    repo_mlp_kernel<<<512, 128>>>(x, W1, b1, W2, b2);
    scan_kernel<<<2, 1024>>>();
    angles_kernel<<<512, 256>>>();
    conv_split_kernel<<<4096, 256>>>(x, 0);
    conv_wT_kernel<<<dim3(32, 32, 4), dim3(32, 32)>>>(Wq, Wk, Wv, Wo);
    mm_mma_kernel<0><<<dim3(8, 32, 3), 256, SMEM_MM>>>(nullptr);
    rope_kernel<<<8192, 256>>>();
    flash_kernel<<<dim3(32, 16, 2), 256>>>();
    conv_split_kernel<<<4096, 256>>>(nullptr, 1);
    mm_mma_kernel<1><<<dim3(8, 32, 1), 256, SMEM_MM>>>(out);
}

// round 5
// speedup vs baseline: 2.4998x; 1.8977x over previous
#include <cuda_runtime.h>
#include <cuda_bf16.h>
#include <math.h>
#include <stdint.h>

#define BB   2
#define SS   2048
#define HH   16
#define DD   64
#define HID  1024
#define PD   128

// ---------------- scratch (device globals — no allocation allowed) ----------------
__device__ __align__(256) float  g_qt[BB*HH*SS*DD];     // Q (b,h,s,d) pre-RoPE fp32
__device__ __align__(256) float  g_kt[BB*HH*SS*DD];     // K (b,h,s,d) pre-RoPE fp32
__device__ __align__(256) float  g_vt[BB*HH*SS*DD];     // V (b,h,s,d) fp32
__device__ float  g_sp[BB*SS];
__device__ double g_posd[BB*SS];
__device__ float  g_cos[BB*SS*32];
__device__ float  g_sin[BB*SS*32];
// bf16 hi/lo operands
__device__ __align__(256) __nv_bfloat16 g_xhi[BB*SS*HID];
__device__ __align__(256) __nv_bfloat16 g_xlo[BB*SS*HID];
__device__ __align__(256) __nv_bfloat16 g_ahi[BB*SS*HID];     // attention out hi
__device__ __align__(256) __nv_bfloat16 g_alo[BB*SS*HID];     // attention out lo
__device__ __align__(256) __nv_bfloat16 g_wthi[4*HID*HID];    // W^T (n,k)
__device__ __align__(256) __nv_bfloat16 g_wtlo[4*HID*HID];
// flash operands (bf16 hi/lo)
__device__ __align__(256) __nv_bfloat16 g_qhi[BB*HH*SS*DD];   // (b,h,s,d), scaled by 1/8
__device__ __align__(256) __nv_bfloat16 g_qlo[BB*HH*SS*DD];
__device__ __align__(256) __nv_bfloat16 g_khi[BB*HH*SS*DD];   // (b,h,s,d)
__device__ __align__(256) __nv_bfloat16 g_klo[BB*HH*SS*DD];
__device__ __align__(256) __nv_bfloat16 g_vthi[BB*HH*DD*SS];  // (b,h,d,s)  V^T
__device__ __align__(256) __nv_bfloat16 g_vtlo[BB*HH*DD*SS];

// ==================== helpers ====================
__device__ __forceinline__ uint32_t smem_u32(const void* p) {
    uint32_t a;
    asm("{ .reg .u64 t; cvta.to.shared.u64 t, %1; cvt.u32.u64 %0, t; }" : "=r"(a) : "l"(p));
    return a;
}
__device__ __forceinline__ void cp_async16(uint32_t dst, const void* src) {
    asm volatile("cp.async.cg.shared.global [%0], [%1], 16;" :: "r"(dst), "l"(src));
}
__device__ __forceinline__ void cp_commit() {
    asm volatile("cp.async.commit_group;" ::: "memory");
}
__device__ __forceinline__ void ldsm_x4(uint32_t* r, uint32_t addr) {
    asm volatile("ldmatrix.sync.aligned.m8n8.x4.shared.b16 {%0,%1,%2,%3}, [%4];"
                 : "=r"(r[0]), "=r"(r[1]), "=r"(r[2]), "=r"(r[3]) : "r"(addr));
}
__device__ __forceinline__ void mma16816(float* c, const uint32_t* a, uint32_t b0, uint32_t b1) {
    asm volatile(
        "mma.sync.aligned.m16n8k16.row.col.f32.bf16.bf16.f32 "
        "{%0,%1,%2,%3}, {%4,%5,%6,%7}, {%8,%9}, {%0,%1,%2,%3};"
        : "+f"(c[0]), "+f"(c[1]), "+f"(c[2]), "+f"(c[3])
        : "r"(a[0]), "r"(a[1]), "r"(a[2]), "r"(a[3]), "r"(b0), "r"(b1));
}
// pack two fp32 -> bf16x2 (lo -> low half, hi -> high half), round-to-nearest
__device__ __forceinline__ uint32_t pack_bf(float lo, float hi) {
    uint32_t r;
    asm("cvt.rn.bf16x2.f32 %0, %1, %2;" : "=r"(r) : "f"(hi), "f"(lo));
    return r;
}
__device__ __forceinline__ float bf16f(float x) {
    return __bfloat162float(__float2bfloat16(x));
}
__device__ __forceinline__ void sp_store(__nv_bfloat16* hi, __nv_bfloat16* lo, size_t o, float v) {
    __nv_bfloat16 h = __float2bfloat16(v);
    hi[o] = h;
    lo[o] = __float2bfloat16(v - __bfloat162float(h));
}

// ==================== RePo MLP ====================
__global__ __launch_bounds__(128) void repo_mlp_kernel(
    const float* __restrict__ x, const float* __restrict__ W1,
    const float* __restrict__ b1, const float* __restrict__ W2,
    const float* __restrict__ b2)
{
    __shared__ float xs[8 * HID];
    __shared__ float red[4][8];
    int tid  = threadIdx.x;
    int row0 = blockIdx.x * 8;
    const float* xg = x + (size_t)row0 * HID;
    #pragma unroll
    for (int i = 0; i < 16; i++) {
        int lin = i * 128 + tid;
        *(float4*)&xs[lin * 4] = *(const float4*)&xg[lin * 4];
    }
    __syncthreads();

    float acc[8];
    #pragma unroll
    for (int t = 0; t < 8; t++) acc[t] = 0.f;
    int p = tid;
    for (int d = 0; d < HID; d++) {
        float w = W1[d * PD + p];
        #pragma unroll
        for (int t = 0; t < 8; t++) acc[t] = fmaf(xs[t * HID + d], w, acc[t]);
    }
    float bb = b1[p];
    float w2 = W2[p];
    float v[8];
    #pragma unroll
    for (int t = 0; t < 8; t++) {
        float z = acc[t] + bb;
        float g = 0.5f * z * (1.f + tanhf(0.7978845608028654f * (z + 0.044715f * z * z * z)));
        v[t] = g * w2;
    }
    int lane = tid & 31, warp = tid >> 5;
    #pragma unroll
    for (int t = 0; t < 8; t++) {
        float s = v[t];
        #pragma unroll
        for (int off = 16; off; off >>= 1) s += __shfl_xor_sync(0xffffffffu, s, off);
        if (lane == 0) red[warp][t] = s;
    }
    __syncthreads();
    if (tid < 8) {
        float r  = red[0][tid] + red[1][tid] + red[2][tid] + red[3][tid] + b2[0];
        float sp = fmaxf(r, 0.f) + log1pf(expf(-fabsf(r)));
        g_sp[row0 + tid] = sp;
    }
}

// ==================== fp64 scan ====================
__global__ __launch_bounds__(1024) void scan_kernel()
{
    __shared__ double sc[1024];
    int b = blockIdx.x, t = threadIdx.x;
    float a0 = g_sp[b * SS + 2 * t];
    float a1 = g_sp[b * SS + 2 * t + 1];
    sc[t] = (double)a0 + (double)a1;
    __syncthreads();
    for (int off = 1; off < 1024; off <<= 1) {
        double v = (t >= off) ? sc[t - off] : 0.0;
        __syncthreads();
        sc[t] += v;
        __syncthreads();
    }
    double excl = (t == 0) ? 0.0 : sc[t - 1];
    g_posd[b * SS + 2 * t]     = excl + (double)a0;
    g_posd[b * SS + 2 * t + 1] = excl + (double)a0 + (double)a1;
}

// ==================== angles ====================
__global__ __launch_bounds__(256) void angles_kernel()
{
    int idx = blockIdx.x * 256 + threadIdx.x;
    int j = idx & 31, bs = idx >> 5;
    double f   = exp(((double)(-2 * j) / 64.0) * 9.210340371976184);
    double ang = g_posd[bs] * f;
    const double twopi = 6.283185307179586476925286766559;
    ang -= floor(ang * (1.0 / twopi)) * twopi;
    float af = (float)ang;
    g_cos[idx] = cosf(af);
    g_sin[idx] = sinf(af);
}

// ==================== fp32 x -> bf16 hi/lo ====================
__global__ __launch_bounds__(256) void conv_split_kernel(const float* __restrict__ src)
{
    int idx = (blockIdx.x * 256 + threadIdx.x) * 4;
    float4 v = *(const float4*)&src[idx];
    ushort4 H, L;
    {
        __nv_bfloat16 h = __float2bfloat16(v.x); H.x = *(unsigned short*)&h;
        __nv_bfloat16 l = __float2bfloat16(v.x - __bfloat162float(h)); L.x = *(unsigned short*)&l;
    }
    {
        __nv_bfloat16 h = __float2bfloat16(v.y); H.y = *(unsigned short*)&h;
        __nv_bfloat16 l = __float2bfloat16(v.y - __bfloat162float(h)); L.y = *(unsigned short*)&l;
    }
    {
        __nv_bfloat16 h = __float2bfloat16(v.z); H.z = *(unsigned short*)&h;
        __nv_bfloat16 l = __float2bfloat16(v.z - __bfloat162float(h)); L.z = *(unsigned short*)&l;
    }
    {
        __nv_bfloat16 h = __float2bfloat16(v.w); H.w = *(unsigned short*)&h;
        __nv_bfloat16 l = __float2bfloat16(v.w - __bfloat162float(h)); L.w = *(unsigned short*)&l;
    }
    *(ushort4*)&g_xhi[idx] = H;
    *(ushort4*)&g_xlo[idx] = L;
}

// ==================== W (k,n) -> W^T (n,k) bf16 hi/lo ====================
__global__ void conv_wT_kernel(const float* __restrict__ Wq, const float* __restrict__ Wk,
                               const float* __restrict__ Wv, const float* __restrict__ Wo)
{
    __shared__ float t[32][33];
    int z = blockIdx.z;
    const float* W = (z == 0) ? Wq : (z == 1) ? Wk : (z == 2) ? Wv : Wo;
    int n0 = blockIdx.x * 32, k0 = blockIdx.y * 32;
    t[threadIdx.y][threadIdx.x] = W[(size_t)(k0 + threadIdx.y) * HID + n0 + threadIdx.x];
    __syncthreads();
    float v = t[threadIdx.x][threadIdx.y];
    size_t o = ((size_t)z << 20) + (size_t)(n0 + threadIdx.y) * HID + k0 + threadIdx.x;
    __nv_bfloat16 h = __float2bfloat16(v);
    g_wthi[o] = h;
    g_wtlo[o] = __float2bfloat16(v - __bfloat162float(h));
}

// ==================== mma.sync bf16x3 GEMM ====================
#define TILE_B   10240
#define BUF_B    (4 * TILE_B)
#define SMEM_MM  (2 * BUF_B)

template<int MODE>
__global__ __launch_bounds__(256) void mm_mma_kernel(float* __restrict__ outp)
{
    extern __shared__ __align__(128) char smem[];
    uint32_t sbase = smem_u32(smem);
    int tid = threadIdx.x;
    int lane = tid & 31, wid = tid >> 5;
    int wm = wid & 3, wn = wid >> 2;

    int n0 = blockIdx.x * 128, m0 = blockIdx.y * 128;
    int z  = (MODE == 0) ? (int)blockIdx.z : 3;
    const __nv_bfloat16* Ahi = ((MODE == 0) ? g_xhi : g_ahi) + (size_t)m0 * HID;
    const __nv_bfloat16* Alo = ((MODE == 0) ? g_xlo : g_alo) + (size_t)m0 * HID;
    const __nv_bfloat16* Bhi = g_wthi + ((size_t)z << 20) + (size_t)n0 * HID;
    const __nv_bfloat16* Blo = g_wtlo + ((size_t)z << 20) + (size_t)n0 * HID;

    float acc[2][8][4];
    #pragma unroll
    for (int i = 0; i < 2; i++)
        #pragma unroll
        for (int j = 0; j < 8; j++)
            #pragma unroll
            for (int q = 0; q < 4; q++) acc[i][j][q] = 0.f;

    int arow = lane & 15,  acg = lane >> 4;
    int brow = (lane & 7) + ((lane >> 4) << 3);
    int bcg  = (lane >> 3) & 1;

    {
        const __nv_bfloat16* bases[4] = {Ahi, Alo, Bhi, Blo};
        #pragma unroll
        for (int it = 0; it < 8; it++) {
            int lin = it * 256 + tid;
            int tile = lin >> 9, idx = lin & 511, r = idx >> 2, cc = idx & 3;
            cp_async16(sbase + tile * TILE_B + r * 80 + cc * 16,
                       bases[tile] + (size_t)r * HID + cc * 8);
        }
        cp_commit();
    }

    for (int c = 0; c < 32; c++) {
        if (c + 1 < 32) {
            int k0 = (c + 1) * 32;
            uint32_t sb = sbase + ((c + 1) & 1) * BUF_B;
            const __nv_bfloat16* bases[4] = {Ahi, Alo, Bhi, Blo};
            #pragma unroll
            for (int it = 0; it < 8; it++) {
                int lin = it * 256 + tid;
                int tile = lin >> 9, idx = lin & 511, r = idx >> 2, cc = idx & 3;
                cp_async16(sb + tile * TILE_B + r * 80 + cc * 16,
                           bases[tile] + (size_t)r * HID + k0 + cc * 8);
            }
            cp_commit();
            asm volatile("cp.async.wait_group 1;" ::: "memory");
        } else {
            asm volatile("cp.async.wait_group 0;" ::: "memory");
        }
        __syncthreads();

        uint32_t sb   = sbase + (c & 1) * BUF_B;
        uint32_t sAhi = sb, sAlo = sb + TILE_B, sBhi = sb + 2 * TILE_B, sBlo = sb + 3 * TILE_B;

        #pragma unroll
        for (int ks = 0; ks < 2; ks++) {
            uint32_t a[2][4], bh[4][4], bl[4][4];
            #pragma unroll
            for (int i = 0; i < 2; i++)
                ldsm_x4(a[i], sAhi + ((wm * 32 + i * 16 + arow) * 40 + ks * 16 + acg * 8) * 2);
            #pragma unroll
            for (int j = 0; j < 4; j++)
                ldsm_x4(bh[j], sBhi + ((wn * 64 + j * 16 + brow) * 40 + ks * 16 + bcg * 8) * 2);
            #pragma unroll
            for (int i = 0; i < 2; i++)
                #pragma unroll
                for (int j = 0; j < 8; j++)
                    mma16816(acc[i][j], a[i], bh[j >> 1][(j & 1) * 2], bh[j >> 1][(j & 1) * 2 + 1]);
            #pragma unroll
            for (int j = 0; j < 4; j++)
                ldsm_x4(bl[j], sBlo + ((wn * 64 + j * 16 + brow) * 40 + ks * 16 + bcg * 8) * 2);
            #pragma unroll
            for (int i = 0; i < 2; i++)
                #pragma unroll
                for (int j = 0; j < 8; j++)
                    mma16816(acc[i][j], a[i], bl[j >> 1][(j & 1) * 2], bl[j >> 1][(j & 1) * 2 + 1]);
            #pragma unroll
            for (int i = 0; i < 2; i++)
                ldsm_x4(a[i], sAlo + ((wm * 32 + i * 16 + arow) * 40 + ks * 16 + acg * 8) * 2);
            #pragma unroll
            for (int i = 0; i < 2; i++)
                #pragma unroll
                for (int j = 0; j < 8; j++)
                    mma16816(acc[i][j], a[i], bh[j >> 1][(j & 1) * 2], bh[j >> 1][(j & 1) * 2 + 1]);
        }
        __syncthreads();
    }

    #pragma unroll
    for (int i = 0; i < 2; i++)
        #pragma unroll
        for (int j = 0; j < 8; j++) {
            int n = n0 + wn * 64 + j * 8 + (lane & 3) * 2;
            #pragma unroll
            for (int half = 0; half < 2; half++) {
                int m = m0 + wm * 32 + i * 16 + (lane >> 2) + half * 8;
                float2 val = make_float2(acc[i][j][half * 2], acc[i][j][half * 2 + 1]);
                if (MODE == 0) {
                    int b = m >> 11, s = m & 2047, h = n >> 6, d = n & 63;
                    float* dst = (z == 0) ? g_qt : (z == 1) ? g_kt : g_vt;
                    *(float2*)(dst + ((size_t)((b * HH + h) * SS + s)) * DD + d) = val;
                } else {
                    *(float2*)(outp + (size_t)m * HID + n) = val;
                }
            }
        }
}

// ==================== RoPE + split to bf16 hi/lo (Q scaled by 1/8) ====================
__global__ __launch_bounds__(256) void rope_split_kernel()
{
    int idx = blockIdx.x * 256 + threadIdx.x;    // (((b*H+h)*S)+s)*32 + j
    int j = idx & 31;
    int s = (idx >> 5) & 2047;
    int h = (idx >> 16) & 15;
    int b = idx >> 20;
    size_t base = ((size_t)((b * HH + h) * SS + s)) * DD;
    int ci = (b * SS + s) * 32 + j;
    float c = g_cos[ci], sn = g_sin[ci];
    float q1 = g_qt[base + j], q2 = g_qt[base + 32 + j];
    float k1 = g_kt[base + j], k2 = g_kt[base + 32 + j];
    float qa = 0.125f * (q1 * c - q2 * sn);
    float qb = 0.125f * (q1 * sn + q2 * c);
    float ka = k1 * c - k2 * sn;
    float kb = k1 * sn + k2 * c;
    sp_store(g_qhi, g_qlo, base + j,      qa);
    sp_store(g_qhi, g_qlo, base + 32 + j, qb);
    sp_store(g_khi, g_klo, base + j,      ka);
    sp_store(g_khi, g_klo, base + 32 + j, kb);
}

// ==================== V transpose + split: (b,h,s,d) -> (b,h,d,s) bf16 hi/lo ====
__global__ void vsplit_kernel()
{
    __shared__ float t[32][33];
    int bh = blockIdx.z;
    int s0 = blockIdx.x * 32, d0 = blockIdx.y * 32;
    t[threadIdx.y][threadIdx.x] =
        g_vt[((size_t)bh * SS + s0 + threadIdx.y) * DD + d0 + threadIdx.x];
    __syncthreads();
    float v = t[threadIdx.x][threadIdx.y];   // V[s0+tx][d0+ty]
    size_t o = (size_t)bh * DD * SS + (size_t)(d0 + threadIdx.y) * SS + s0 + threadIdx.x;
    sp_store(g_vthi, g_vtlo, o, v);
}

// ==================== Flash attention, mma.sync bf16x3 ====================
// BQ=128, BKV=64. 8 warps, warp = 16 q-rows x full chunk.
// smem: 2 buffers x {Khi, Klo, Vthi, Vtlo}, each 64 rows x 72 bf16 (144B stride)
#define FT     9216                 // 64*144
#define FBUF   (4 * FT)             // 36864
#define SMEM_F (2 * FBUF)           // 73728

__global__ __launch_bounds__(256) void flash_mma_kernel()
{
    extern __shared__ __align__(128) char fsm[];
    uint32_t sbase = smem_u32(fsm);
    int tid = threadIdx.x, lane = tid & 31, w = tid >> 5;
    int qt = blockIdx.x, bh = blockIdx.y;
    int b = bh >> 4, h = bh & 15;

    const __nv_bfloat16* Qhi  = g_qhi  + ((size_t)bh * SS + qt * 128) * DD;
    const __nv_bfloat16* Qlo  = g_qlo  + ((size_t)bh * SS + qt * 128) * DD;
    const __nv_bfloat16* Khi  = g_khi  + (size_t)bh * SS * DD;
    const __nv_bfloat16* Klo  = g_klo  + (size_t)bh * SS * DD;
    const __nv_bfloat16* Vthi = g_vthi + (size_t)bh * DD * SS;
    const __nv_bfloat16* Vtlo = g_vtlo + (size_t)bh * DD * SS;

    int arow = lane & 15, acg = lane >> 4;
    int brow = (lane & 7) + ((lane >> 4) << 3), bcg = (lane >> 3) & 1;

    // ---- stage Q (hi at sbase, lo at sbase+18432), extract A-frags ----
    #pragma unroll
    for (int it = 0; it < 4; it++) {
        int lin = it * 256 + tid;            // 0..1023
        int r = lin >> 3, seg = lin & 7;
        cp_async16(sbase +         r * 144 + seg * 16, Qhi + (size_t)r * DD + seg * 8);
        cp_async16(sbase + 18432 + r * 144 + seg * 16, Qlo + (size_t)r * DD + seg * 8);
    }
    cp_commit();
    asm volatile("cp.async.wait_group 0;" ::: "memory");
    __syncthreads();
    uint32_t aqh[4][4], aql[4][4];
    #pragma unroll
    for (int kb = 0; kb < 4; kb++) {
        ldsm_x4(aqh[kb], sbase +         ((w * 16 + arow) * 72 + kb * 16 + acg * 8) * 2);
        ldsm_x4(aql[kb], sbase + 18432 + ((w * 16 + arow) * 72 + kb * 16 + acg * 8) * 2);
    }
    __syncthreads();

    float s[8][4], o[8][4];
    #pragma unroll
    for (int j = 0; j < 8; j++)
        #pragma unroll
        for (int q = 0; q < 4; q++) o[j][q] = 0.f;
    float m0 = -1e30f, m1 = -1e30f, l0 = 0.f, l1 = 0.f;

    // prefetch chunk 0
    {
        uint32_t sb = sbase;
        #pragma unroll
        for (int it = 0; it < 8; it++) {
            int lin = it * 256 + tid;
            int tile = lin >> 9, idx = lin & 511;
            int r = idx >> 3, seg = idx & 7;
            const __nv_bfloat16* src =
                (tile == 0) ? Khi  + (size_t)r * DD + seg * 8 :
                (tile == 1) ? Klo  + (size_t)r * DD + seg * 8 :
                (tile == 2) ? Vthi + (size_t)r * SS + seg * 8 :
                              Vtlo + (size_t)r * SS + seg * 8;
            cp_async16(sb + tile * FT + r * 144 + seg * 16, src);
        }
        cp_commit();
    }

    for (int c = 0; c < 32; c++) {
        if (c + 1 < 32) {
            int kbase = (c + 1) * 64;
            uint32_t sb = sbase + ((c + 1) & 1) * FBUF;
            #pragma unroll
            for (int it = 0; it < 8; it++) {
                int lin = it * 256 + tid;
                int tile = lin >> 9, idx = lin & 511;
                int r = idx >> 3, seg = idx & 7;
                const __nv_bfloat16* src =
                    (tile == 0) ? Khi  + (size_t)(kbase + r) * DD + seg * 8 :
                    (tile == 1) ? Klo  + (size_t)(kbase + r) * DD + seg * 8 :
                    (tile == 2) ? Vthi + (size_t)r * SS + kbase + seg * 8 :
                                  Vtlo + (size_t)r * SS + kbase + seg * 8;
                cp_async16(sb + tile * FT + r * 144 + seg * 16, src);
            }
            cp_commit();
            asm volatile("cp.async.wait_group 1;" ::: "memory");
        } else {
            asm volatile("cp.async.wait_group 0;" ::: "memory");
        }
        __syncthreads();

        uint32_t sb = sbase + (c & 1) * FBUF;

        // ---- S = Qhi*Khi + Qhi*Klo + Qlo*Khi ----
        #pragma unroll
        for (int j = 0; j < 8; j++) { s[j][0] = s[j][1] = s[j][2] = s[j][3] = 0.f; }
        #pragma unroll
        for (int kb = 0; kb < 4; kb++) {
            uint32_t kh[4][4], kl[4][4];
            #pragma unroll
            for (int j = 0; j < 4; j++)
                ldsm_x4(kh[j], sb + ((j * 16 + brow) * 72 + kb * 16 + bcg * 8) * 2);
            #pragma unroll
            for (int j = 0; j < 8; j++)
                mma16816(s[j], aqh[kb], kh[j >> 1][(j & 1) * 2], kh[j >> 1][(j & 1) * 2 + 1]);
            #pragma unroll
            for (int j = 0; j < 4; j++)
                ldsm_x4(kl[j], sb + FT + ((j * 16 + brow) * 72 + kb * 16 + bcg * 8) * 2);
            #pragma unroll
            for (int j = 0; j < 8; j++)
                mma16816(s[j], aqh[kb], kl[j >> 1][(j & 1) * 2], kl[j >> 1][(j & 1) * 2 + 1]);
            #pragma unroll
            for (int j = 0; j < 8; j++)
                mma16816(s[j], aql[kb], kh[j >> 1][(j & 1) * 2], kh[j >> 1][(j & 1) * 2 + 1]);
        }

        // ---- online softmax ----
        float mx0 = s[0][0], mx1 = s[0][2];
        #pragma unroll
        for (int j = 0; j < 8; j++) {
            mx0 = fmaxf(mx0, fmaxf(s[j][0], s[j][1]));
            mx1 = fmaxf(mx1, fmaxf(s[j][2], s[j][3]));
        }
        mx0 = fmaxf(mx0, __shfl_xor_sync(0xffffffffu, mx0, 1));
        mx0 = fmaxf(mx0, __shfl_xor_sync(0xffffffffu, mx0, 2));
        mx1 = fmaxf(mx1, __shfl_xor_sync(0xffffffffu, mx1, 1));
        mx1 = fmaxf(mx1, __shfl_xor_sync(0xffffffffu, mx1, 2));
        float mn0 = fmaxf(m0, mx0), mn1 = fmaxf(m1, mx1);
        float al0 = __expf(m0 - mn0), al1 = __expf(m1 - mn1);
        m0 = mn0; m1 = mn1;
        float sum0 = 0.f, sum1 = 0.f;
        #pragma unroll
        for (int j = 0; j < 8; j++) {
            s[j][0] = __expf(s[j][0] - mn0);
            s[j][1] = __expf(s[j][1] - mn0);
            s[j][2] = __expf(s[j][2] - mn1);
            s[j][3] = __expf(s[j][3] - mn1);
            sum0 += s[j][0] + s[j][1];
            sum1 += s[j][2] + s[j][3];
        }
        sum0 += __shfl_xor_sync(0xffffffffu, sum0, 1);
        sum0 += __shfl_xor_sync(0xffffffffu, sum0, 2);
        sum1 += __shfl_xor_sync(0xffffffffu, sum1, 1);
        sum1 += __shfl_xor_sync(0xffffffffu, sum1, 2);
        l0 = l0 * al0 + sum0;
        l1 = l1 * al1 + sum1;
        #pragma unroll
        for (int j = 0; j < 8; j++) {
            o[j][0] *= al0; o[j][1] *= al0; o[j][2] *= al1; o[j][3] *= al1;
        }

        // ---- O += Phi*Vhi + Phi*Vlo + Plo*Vhi ----
        #pragma unroll
        for (int kb = 0; kb < 4; kb++) {
            float e0 = s[2 * kb][0],     e1 = s[2 * kb][1];
            float e2 = s[2 * kb][2],     e3 = s[2 * kb][3];
            float e4 = s[2 * kb + 1][0], e5 = s[2 * kb + 1][1];
            float e6 = s[2 * kb + 1][2], e7 = s[2 * kb + 1][3];
            uint32_t ph[4], pl[4];
            ph[0] = pack_bf(e0, e1);  ph[1] = pack_bf(e2, e3);
            ph[2] = pack_bf(e4, e5);  ph[3] = pack_bf(e6, e7);
            pl[0] = pack_bf(e0 - bf16f(e0), e1 - bf16f(e1));
            pl[1] = pack_bf(e2 - bf16f(e2), e3 - bf16f(e3));
            pl[2] = pack_bf(e4 - bf16f(e4), e5 - bf16f(e5));
            pl[3] = pack_bf(e6 - bf16f(e6), e7 - bf16f(e7));

            uint32_t vh[4][4], vl[4][4];
            #pragma unroll
            for (int j = 0; j < 4; j++)
                ldsm_x4(vh[j], sb + 2 * FT + ((j * 16 + brow) * 72 + kb * 16 + bcg * 8) * 2);
            #pragma unroll
            for (int j = 0; j < 8; j++)
                mma16816(o[j], ph, vh[j >> 1][(j & 1) * 2], vh[j >> 1][(j & 1) * 2 + 1]);
            #pragma unroll
            for (int j = 0; j < 4; j++)
                ldsm_x4(vl[j], sb + 3 * FT + ((j * 16 + brow) * 72 + kb * 16 + bcg * 8) * 2);
            #pragma unroll
            for (int j = 0; j < 8; j++)
                mma16816(o[j], ph, vl[j >> 1][(j & 1) * 2], vl[j >> 1][(j & 1) * 2 + 1]);
            #pragma unroll
            for (int j = 0; j < 8; j++)
                mma16816(o[j], pl, vh[j >> 1][(j & 1) * 2], vh[j >> 1][(j & 1) * 2 + 1]);
        }
        __syncthreads();
    }

    // ---- epilogue: O/l -> bf16 hi/lo into oproj A operand ----
    float i0 = 1.f / l0, i1 = 1.f / l1;
    int r0 = qt * 128 + w * 16 + (lane >> 2);
    #pragma unroll
    for (int j = 0; j < 8; j++) {
        int n = h * 64 + j * 8 + (lane & 3) * 2;
        size_t o0 = ((size_t)(b * SS) + r0) * HID + n;
        size_t o1 = o0 + 8 * HID;
        float a0 = o[j][0] * i0, a1 = o[j][1] * i0;
        float a2 = o[j][2] * i1, a3 = o[j][3] * i1;
        *(uint32_t*)&g_ahi[o0] = pack_bf(a0, a1);
        *(uint32_t*)&g_alo[o0] = pack_bf(a0 - bf16f(a0), a1 - bf16f(a1));
        *(uint32_t*)&g_ahi[o1] = pack_bf(a2, a3);
        *(uint32_t*)&g_alo[o1] = pack_bf(a2 - bf16f(a2), a3 - bf16f(a3));
    }
}

// ==================== launch ====================
extern "C" void kernel_launch(void* const* d_in, const int* in_sizes, int n_in,
                              void* d_out, int out_size)
{
    const float* x  = (const float*)d_in[0];
    const float* Wq = (const float*)d_in[1];
    const float* Wk = (const float*)d_in[2];
    const float* Wv = (const float*)d_in[3];
    const float* Wo = (const float*)d_in[4];
    const float* W1 = (const float*)d_in[5];
    const float* b1 = (const float*)d_in[6];
    const float* W2 = (const float*)d_in[7];
    const float* b2 = (const float*)d_in[8];
    float* out = (float*)d_out;

    cudaFuncSetAttribute(mm_mma_kernel<0>, cudaFuncAttributeMaxDynamicSharedMemorySize, SMEM_MM);
    cudaFuncSetAttribute(mm_mma_kernel<1>, cudaFuncAttributeMaxDynamicSharedMemorySize, SMEM_MM);
    cudaFuncSetAttribute(flash_mma_kernel, cudaFuncAttributeMaxDynamicSharedMemorySize, SMEM_F);

    repo_mlp_kernel<<<512, 128>>>(x, W1, b1, W2, b2);
    scan_kernel<<<2, 1024>>>();
    angles_kernel<<<512, 256>>>();
    conv_split_kernel<<<4096, 256>>>(x);
    conv_wT_kernel<<<dim3(32, 32, 4), dim3(32, 32)>>>(Wq, Wk, Wv, Wo);
    mm_mma_kernel<0><<<dim3(8, 32, 3), 256, SMEM_MM>>>(nullptr);
    rope_split_kernel<<<8192, 256>>>();
    vsplit_kernel<<<dim3(64, 2, 32), dim3(32, 32)>>>();
    flash_mma_kernel<<<dim3(16, 32), 256, SMEM_F>>>();
    mm_mma_kernel<1><<<dim3(8, 32, 1), 256, SMEM_MM>>>(out);
}

// round 6
// speedup vs baseline: 2.6746x; 1.0699x over previous
#include <cuda_runtime.h>
#include <cuda_bf16.h>
#include <math.h>
#include <stdint.h>

#define BB   2
#define SS   2048
#define HH   16
#define DD   64
#define HID  1024
#define PD   128

// ---------------- scratch (device globals — no allocation allowed) ----------------
__device__ float  g_sp[BB*SS];
__device__ double g_posd[BB*SS];
__device__ __align__(256) float g_cos[BB*SS*32];
__device__ __align__(256) float g_sin[BB*SS*32];
// bf16 hi/lo operands
__device__ __align__(256) __nv_bfloat16 g_xhi[BB*SS*HID];
__device__ __align__(256) __nv_bfloat16 g_xlo[BB*SS*HID];
__device__ __align__(256) __nv_bfloat16 g_ahi[BB*SS*HID];     // attention out hi
__device__ __align__(256) __nv_bfloat16 g_alo[BB*SS*HID];     // attention out lo
__device__ __align__(256) __nv_bfloat16 g_wthi[4*HID*HID];    // W^T (n,k)
__device__ __align__(256) __nv_bfloat16 g_wtlo[4*HID*HID];
// flash operands (bf16 hi/lo), written directly by mm<0> epilogue
__device__ __align__(256) __nv_bfloat16 g_qhi[BB*HH*SS*DD];   // (b,h,s,d), RoPE'd, scaled 1/8
__device__ __align__(256) __nv_bfloat16 g_qlo[BB*HH*SS*DD];
__device__ __align__(256) __nv_bfloat16 g_khi[BB*HH*SS*DD];   // (b,h,s,d), RoPE'd
__device__ __align__(256) __nv_bfloat16 g_klo[BB*HH*SS*DD];
__device__ __align__(256) __nv_bfloat16 g_vthi[BB*HH*DD*SS];  // (b,h,d,s)  V^T
__device__ __align__(256) __nv_bfloat16 g_vtlo[BB*HH*DD*SS];

// ==================== helpers ====================
__device__ __forceinline__ uint32_t smem_u32(const void* p) {
    uint32_t a;
    asm("{ .reg .u64 t; cvta.to.shared.u64 t, %1; cvt.u32.u64 %0, t; }" : "=r"(a) : "l"(p));
    return a;
}
__device__ __forceinline__ void cp_async16(uint32_t dst, const void* src) {
    asm volatile("cp.async.cg.shared.global [%0], [%1], 16;" :: "r"(dst), "l"(src));
}
__device__ __forceinline__ void cp_commit() {
    asm volatile("cp.async.commit_group;" ::: "memory");
}
__device__ __forceinline__ void ldsm_x4(uint32_t* r, uint32_t addr) {
    asm volatile("ldmatrix.sync.aligned.m8n8.x4.shared.b16 {%0,%1,%2,%3}, [%4];"
                 : "=r"(r[0]), "=r"(r[1]), "=r"(r[2]), "=r"(r[3]) : "r"(addr));
}
__device__ __forceinline__ void mma16816(float* c, const uint32_t* a, uint32_t b0, uint32_t b1) {
    asm volatile(
        "mma.sync.aligned.m16n8k16.row.col.f32.bf16.bf16.f32 "
        "{%0,%1,%2,%3}, {%4,%5,%6,%7}, {%8,%9}, {%0,%1,%2,%3};"
        : "+f"(c[0]), "+f"(c[1]), "+f"(c[2]), "+f"(c[3])
        : "r"(a[0]), "r"(a[1]), "r"(a[2]), "r"(a[3]), "r"(b0), "r"(b1));
}
// pack two fp32 -> bf16x2 (first arg -> low half)
__device__ __forceinline__ uint32_t pack_bf(float lo, float hi) {
    uint32_t r;
    asm("cvt.rn.bf16x2.f32 %0, %1, %2;" : "=r"(r) : "f"(hi), "f"(lo));
    return r;
}
__device__ __forceinline__ float bf16f(float x) {
    return __bfloat162float(__float2bfloat16(x));
}
__device__ __forceinline__ void sp_store(__nv_bfloat16* hi, __nv_bfloat16* lo, size_t o, float v) {
    __nv_bfloat16 h = __float2bfloat16(v);
    hi[o] = h;
    lo[o] = __float2bfloat16(v - __bfloat162float(h));
}

// ==================== RePo MLP ====================
__global__ __launch_bounds__(128) void repo_mlp_kernel(
    const float* __restrict__ x, const float* __restrict__ W1,
    const float* __restrict__ b1, const float* __restrict__ W2,
    const float* __restrict__ b2)
{
    __shared__ float xs[8 * HID];
    __shared__ float red[4][8];
    int tid  = threadIdx.x;
    int row0 = blockIdx.x * 8;
    const float* xg = x + (size_t)row0 * HID;
    #pragma unroll
    for (int i = 0; i < 16; i++) {
        int lin = i * 128 + tid;
        *(float4*)&xs[lin * 4] = *(const float4*)&xg[lin * 4];
    }
    __syncthreads();

    float acc[8];
    #pragma unroll
    for (int t = 0; t < 8; t++) acc[t] = 0.f;
    int p = tid;
    for (int d = 0; d < HID; d++) {
        float w = W1[d * PD + p];
        #pragma unroll
        for (int t = 0; t < 8; t++) acc[t] = fmaf(xs[t * HID + d], w, acc[t]);
    }
    float bb = b1[p];
    float w2 = W2[p];
    float v[8];
    #pragma unroll
    for (int t = 0; t < 8; t++) {
        float z = acc[t] + bb;
        float g = 0.5f * z * (1.f + tanhf(0.7978845608028654f * (z + 0.044715f * z * z * z)));
        v[t] = g * w2;
    }
    int lane = tid & 31, warp = tid >> 5;
    #pragma unroll
    for (int t = 0; t < 8; t++) {
        float s = v[t];
        #pragma unroll
        for (int off = 16; off; off >>= 1) s += __shfl_xor_sync(0xffffffffu, s, off);
        if (lane == 0) red[warp][t] = s;
    }
    __syncthreads();
    if (tid < 8) {
        float r  = red[0][tid] + red[1][tid] + red[2][tid] + red[3][tid] + b2[0];
        float sp = fmaxf(r, 0.f) + log1pf(expf(-fabsf(r)));
        g_sp[row0 + tid] = sp;
    }
}

// ==================== fp64 scan ====================
__global__ __launch_bounds__(1024) void scan_kernel()
{
    __shared__ double sc[1024];
    int b = blockIdx.x, t = threadIdx.x;
    float a0 = g_sp[b * SS + 2 * t];
    float a1 = g_sp[b * SS + 2 * t + 1];
    sc[t] = (double)a0 + (double)a1;
    __syncthreads();
    for (int off = 1; off < 1024; off <<= 1) {
        double v = (t >= off) ? sc[t - off] : 0.0;
        __syncthreads();
        sc[t] += v;
        __syncthreads();
    }
    double excl = (t == 0) ? 0.0 : sc[t - 1];
    g_posd[b * SS + 2 * t]     = excl + (double)a0;
    g_posd[b * SS + 2 * t + 1] = excl + (double)a0 + (double)a1;
}

// ==================== angles ====================
__global__ __launch_bounds__(256) void angles_kernel()
{
    int idx = blockIdx.x * 256 + threadIdx.x;
    int j = idx & 31, bs = idx >> 5;
    double f   = exp(((double)(-2 * j) / 64.0) * 9.210340371976184);
    double ang = g_posd[bs] * f;
    const double twopi = 6.283185307179586476925286766559;
    ang -= floor(ang * (1.0 / twopi)) * twopi;
    float af = (float)ang;
    g_cos[idx] = cosf(af);
    g_sin[idx] = sinf(af);
}

// ==================== fp32 x -> bf16 hi/lo ====================
__global__ __launch_bounds__(256) void conv_split_kernel(const float* __restrict__ src)
{
    int idx = (blockIdx.x * 256 + threadIdx.x) * 4;
    float4 v = *(const float4*)&src[idx];
    ushort4 H, L;
    {
        __nv_bfloat16 h = __float2bfloat16(v.x); H.x = *(unsigned short*)&h;
        __nv_bfloat16 l = __float2bfloat16(v.x - __bfloat162float(h)); L.x = *(unsigned short*)&l;
    }
    {
        __nv_bfloat16 h = __float2bfloat16(v.y); H.y = *(unsigned short*)&h;
        __nv_bfloat16 l = __float2bfloat16(v.y - __bfloat162float(h)); L.y = *(unsigned short*)&l;
    }
    {
        __nv_bfloat16 h = __float2bfloat16(v.z); H.z = *(unsigned short*)&h;
        __nv_bfloat16 l = __float2bfloat16(v.z - __bfloat162float(h)); L.z = *(unsigned short*)&l;
    }
    {
        __nv_bfloat16 h = __float2bfloat16(v.w); H.w = *(unsigned short*)&h;
        __nv_bfloat16 l = __float2bfloat16(v.w - __bfloat162float(h)); L.w = *(unsigned short*)&l;
    }
    *(ushort4*)&g_xhi[idx] = H;
    *(ushort4*)&g_xlo[idx] = L;
}

// ==================== W (k,n) -> W^T (n,k) bf16 hi/lo ====================
__global__ void conv_wT_kernel(const float* __restrict__ Wq, const float* __restrict__ Wk,
                               const float* __restrict__ Wv, const float* __restrict__ Wo)
{
    __shared__ float t[32][33];
    int z = blockIdx.z;
    const float* W = (z == 0) ? Wq : (z == 1) ? Wk : (z == 2) ? Wv : Wo;
    int n0 = blockIdx.x * 32, k0 = blockIdx.y * 32;
    t[threadIdx.y][threadIdx.x] = W[(size_t)(k0 + threadIdx.y) * HID + n0 + threadIdx.x];
    __syncthreads();
    float v = t[threadIdx.x][threadIdx.y];
    size_t o = ((size_t)z << 20) + (size_t)(n0 + threadIdx.y) * HID + k0 + threadIdx.x;
    __nv_bfloat16 h = __float2bfloat16(v);
    g_wthi[o] = h;
    g_wtlo[o] = __float2bfloat16(v - __bfloat162float(h));
}

// ==================== mma.sync bf16x3 GEMM ====================
// MODE 0: A = x hi/lo, B = wt[z]; fused epilogue:
//          z=0/1 -> RoPE + split -> g_q{hi,lo} / g_k{hi,lo} (Q scaled 1/8)
//          z=2   -> transpose + split -> g_vt{hi,lo} (b,h,d,s)
// MODE 1: A = attention out hi/lo, B = wt[3]; row-major fp32 -> outp
#define TILE_B   10240
#define BUF_B    (4 * TILE_B)
#define SMEM_MM  (2 * BUF_B)

template<int MODE>
__global__ __launch_bounds__(256) void mm_mma_kernel(float* __restrict__ outp)
{
    extern __shared__ __align__(128) char smem[];
    uint32_t sbase = smem_u32(smem);
    int tid = threadIdx.x;
    int lane = tid & 31, wid = tid >> 5;
    int wm = wid & 3, wn = wid >> 2;

    int n0 = blockIdx.x * 128, m0 = blockIdx.y * 128;
    int z  = (MODE == 0) ? (int)blockIdx.z : 3;
    const __nv_bfloat16* Ahi = ((MODE == 0) ? g_xhi : g_ahi) + (size_t)m0 * HID;
    const __nv_bfloat16* Alo = ((MODE == 0) ? g_xlo : g_alo) + (size_t)m0 * HID;
    const __nv_bfloat16* Bhi = g_wthi + ((size_t)z << 20) + (size_t)n0 * HID;
    const __nv_bfloat16* Blo = g_wtlo + ((size_t)z << 20) + (size_t)n0 * HID;

    float acc[2][8][4];
    #pragma unroll
    for (int i = 0; i < 2; i++)
        #pragma unroll
        for (int j = 0; j < 8; j++)
            #pragma unroll
            for (int q = 0; q < 4; q++) acc[i][j][q] = 0.f;

    int arow = lane & 15,  acg = lane >> 4;
    int brow = (lane & 7) + ((lane >> 4) << 3);
    int bcg  = (lane >> 3) & 1;

    {
        const __nv_bfloat16* bases[4] = {Ahi, Alo, Bhi, Blo};
        #pragma unroll
        for (int it = 0; it < 8; it++) {
            int lin = it * 256 + tid;
            int tile = lin >> 9, idx = lin & 511, r = idx >> 2, cc = idx & 3;
            cp_async16(sbase + tile * TILE_B + r * 80 + cc * 16,
                       bases[tile] + (size_t)r * HID + cc * 8);
        }
        cp_commit();
    }

    for (int c = 0; c < 32; c++) {
        if (c + 1 < 32) {
            int k0 = (c + 1) * 32;
            uint32_t sb = sbase + ((c + 1) & 1) * BUF_B;
            const __nv_bfloat16* bases[4] = {Ahi, Alo, Bhi, Blo};
            #pragma unroll
            for (int it = 0; it < 8; it++) {
                int lin = it * 256 + tid;
                int tile = lin >> 9, idx = lin & 511, r = idx >> 2, cc = idx & 3;
                cp_async16(sb + tile * TILE_B + r * 80 + cc * 16,
                           bases[tile] + (size_t)r * HID + k0 + cc * 8);
            }
            cp_commit();
            asm volatile("cp.async.wait_group 1;" ::: "memory");
        } else {
            asm volatile("cp.async.wait_group 0;" ::: "memory");
        }
        __syncthreads();

        uint32_t sb   = sbase + (c & 1) * BUF_B;
        uint32_t sAhi = sb, sAlo = sb + TILE_B, sBhi = sb + 2 * TILE_B, sBlo = sb + 3 * TILE_B;

        #pragma unroll
        for (int ks = 0; ks < 2; ks++) {
            uint32_t a[2][4], bh[4][4], bl[4][4];
            #pragma unroll
            for (int i = 0; i < 2; i++)
                ldsm_x4(a[i], sAhi + ((wm * 32 + i * 16 + arow) * 40 + ks * 16 + acg * 8) * 2);
            #pragma unroll
            for (int j = 0; j < 4; j++)
                ldsm_x4(bh[j], sBhi + ((wn * 64 + j * 16 + brow) * 40 + ks * 16 + bcg * 8) * 2);
            #pragma unroll
            for (int i = 0; i < 2; i++)
                #pragma unroll
                for (int j = 0; j < 8; j++)
                    mma16816(acc[i][j], a[i], bh[j >> 1][(j & 1) * 2], bh[j >> 1][(j & 1) * 2 + 1]);
            #pragma unroll
            for (int j = 0; j < 4; j++)
                ldsm_x4(bl[j], sBlo + ((wn * 64 + j * 16 + brow) * 40 + ks * 16 + bcg * 8) * 2);
            #pragma unroll
            for (int i = 0; i < 2; i++)
                #pragma unroll
                for (int j = 0; j < 8; j++)
                    mma16816(acc[i][j], a[i], bl[j >> 1][(j & 1) * 2], bl[j >> 1][(j & 1) * 2 + 1]);
            #pragma unroll
            for (int i = 0; i < 2; i++)
                ldsm_x4(a[i], sAlo + ((wm * 32 + i * 16 + arow) * 40 + ks * 16 + acg * 8) * 2);
            #pragma unroll
            for (int i = 0; i < 2; i++)
                #pragma unroll
                for (int j = 0; j < 8; j++)
                    mma16816(acc[i][j], a[i], bh[j >> 1][(j & 1) * 2], bh[j >> 1][(j & 1) * 2 + 1]);
        }
        __syncthreads();
    }

    // ---- epilogue ----
    if (MODE == 1) {
        #pragma unroll
        for (int i = 0; i < 2; i++)
            #pragma unroll
            for (int j = 0; j < 8; j++) {
                int n = n0 + wn * 64 + j * 8 + (lane & 3) * 2;
                #pragma unroll
                for (int half = 0; half < 2; half++) {
                    int m = m0 + wm * 32 + i * 16 + (lane >> 2) + half * 8;
                    *(float2*)(outp + (size_t)m * HID + n) =
                        make_float2(acc[i][j][half * 2], acc[i][j][half * 2 + 1]);
                }
            }
        return;
    }

    // MODE 0 fused epilogues
    int h = (n0 + wn * 64) >> 6;          // head for this warp's 64-column span
    if (z == 2) {
        // V: transpose to (b,h,d,s) + hi/lo split
        #pragma unroll
        for (int i = 0; i < 2; i++)
            #pragma unroll
            for (int half = 0; half < 2; half++) {
                int m = m0 + wm * 32 + i * 16 + (lane >> 2) + half * 8;
                int b = m >> 11, s = m & 2047;
                size_t basev = ((size_t)(b * HH + h)) * DD * SS + s;
                #pragma unroll
                for (int j = 0; j < 8; j++) {
                    int d = j * 8 + (lane & 3) * 2;
                    float v0 = acc[i][j][half * 2];
                    float v1 = acc[i][j][half * 2 + 1];
                    sp_store(g_vthi, g_vtlo, basev + (size_t)d * SS, v0);
                    sp_store(g_vthi, g_vtlo, basev + (size_t)(d + 1) * SS, v1);
                }
            }
    } else {
        // Q/K: RoPE in-register + hi/lo split; Q scaled by 1/8
        __nv_bfloat16* dhi = (z == 0) ? g_qhi : g_khi;
        __nv_bfloat16* dlo = (z == 0) ? g_qlo : g_klo;
        float qscale = (z == 0) ? 0.125f : 1.0f;
        #pragma unroll
        for (int i = 0; i < 2; i++)
            #pragma unroll
            for (int half = 0; half < 2; half++) {
                int m = m0 + wm * 32 + i * 16 + (lane >> 2) + half * 8;
                int b = m >> 11, s = m & 2047;
                size_t baseo = ((size_t)((b * HH + h) * SS + s)) * DD;
                int cbase = (b * SS + s) * 32;
                #pragma unroll
                for (int j = 0; j < 4; j++) {
                    int d = j * 8 + (lane & 3) * 2;       // 0..30
                    float c0 = g_cos[cbase + d],     sn0 = g_sin[cbase + d];
                    float c1 = g_cos[cbase + d + 1], sn1 = g_sin[cbase + d + 1];
                    float t1a = acc[i][j][half * 2],     t1b = acc[i][j][half * 2 + 1];
                    float t2a = acc[i][j + 4][half * 2], t2b = acc[i][j + 4][half * 2 + 1];
                    float ra  = qscale * (t1a * c0 - t2a * sn0);
                    float rb  = qscale * (t1b * c1 - t2b * sn1);
                    float r2a = qscale * (t1a * sn0 + t2a * c0);
                    float r2b = qscale * (t1b * sn1 + t2b * c1);
                    __nv_bfloat16 ha = __float2bfloat16(ra), hb = __float2bfloat16(rb);
                    *(uint32_t*)&dhi[baseo + d] =
                        ((uint32_t)*(unsigned short*)&hb << 16) | *(unsigned short*)&ha;
                    *(uint32_t*)&dlo[baseo + d] =
                        pack_bf(ra - __bfloat162float(ha), rb - __bfloat162float(hb));
                    __nv_bfloat16 h2a = __float2bfloat16(r2a), h2b = __float2bfloat16(r2b);
                    *(uint32_t*)&dhi[baseo + d + 32] =
                        ((uint32_t)*(unsigned short*)&h2b << 16) | *(unsigned short*)&h2a;
                    *(uint32_t*)&dlo[baseo + d + 32] =
                        pack_bf(r2a - __bfloat162float(h2a), r2b - __bfloat162float(h2b));
                }
            }
    }
}

// ==================== Flash attention, mma.sync bf16x3 ====================
#define FT     9216                 // 64*144
#define FBUF   (4 * FT)             // 36864
#define SMEM_F (2 * FBUF)           // 73728

__global__ __launch_bounds__(256) void flash_mma_kernel()
{
    extern __shared__ __align__(128) char fsm[];
    uint32_t sbase = smem_u32(fsm);
    int tid = threadIdx.x, lane = tid & 31, w = tid >> 5;
    int qt = blockIdx.x, bh = blockIdx.y;
    int b = bh >> 4, h = bh & 15;

    const __nv_bfloat16* Qhi  = g_qhi  + ((size_t)bh * SS + qt * 128) * DD;
    const __nv_bfloat16* Qlo  = g_qlo  + ((size_t)bh * SS + qt * 128) * DD;
    const __nv_bfloat16* Khi  = g_khi  + (size_t)bh * SS * DD;
    const __nv_bfloat16* Klo  = g_klo  + (size_t)bh * SS * DD;
    const __nv_bfloat16* Vthi = g_vthi + (size_t)bh * DD * SS;
    const __nv_bfloat16* Vtlo = g_vtlo + (size_t)bh * DD * SS;

    int arow = lane & 15, acg = lane >> 4;
    int brow = (lane & 7) + ((lane >> 4) << 3), bcg = (lane >> 3) & 1;

    #pragma unroll
    for (int it = 0; it < 4; it++) {
        int lin = it * 256 + tid;
        int r = lin >> 3, seg = lin & 7;
        cp_async16(sbase +         r * 144 + seg * 16, Qhi + (size_t)r * DD + seg * 8);
        cp_async16(sbase + 18432 + r * 144 + seg * 16, Qlo + (size_t)r * DD + seg * 8);
    }
    cp_commit();
    asm volatile("cp.async.wait_group 0;" ::: "memory");
    __syncthreads();
    uint32_t aqh[4][4], aql[4][4];
    #pragma unroll
    for (int kb = 0; kb < 4; kb++) {
        ldsm_x4(aqh[kb], sbase +         ((w * 16 + arow) * 72 + kb * 16 + acg * 8) * 2);
        ldsm_x4(aql[kb], sbase + 18432 + ((w * 16 + arow) * 72 + kb * 16 + acg * 8) * 2);
    }
    __syncthreads();

    float s[8][4], o[8][4];
    #pragma unroll
    for (int j = 0; j < 8; j++)
        #pragma unroll
        for (int q = 0; q < 4; q++) o[j][q] = 0.f;
    float m0 = -1e30f, m1 = -1e30f, l0 = 0.f, l1 = 0.f;

    {
        uint32_t sb = sbase;
        #pragma unroll
        for (int it = 0; it < 8; it++) {
            int lin = it * 256 + tid;
            int tile = lin >> 9, idx = lin & 511;
            int r = idx >> 3, seg = idx & 7;
            const __nv_bfloat16* src =
                (tile == 0) ? Khi  + (size_t)r * DD + seg * 8 :
                (tile == 1) ? Klo  + (size_t)r * DD + seg * 8 :
                (tile == 2) ? Vthi + (size_t)r * SS + seg * 8 :
                              Vtlo + (size_t)r * SS + seg * 8;
            cp_async16(sb + tile * FT + r * 144 + seg * 16, src);
        }
        cp_commit();
    }

    for (int c = 0; c < 32; c++) {
        if (c + 1 < 32) {
            int kbase = (c + 1) * 64;
            uint32_t sb = sbase + ((c + 1) & 1) * FBUF;
            #pragma unroll
            for (int it = 0; it < 8; it++) {
                int lin = it * 256 + tid;
                int tile = lin >> 9, idx = lin & 511;
                int r = idx >> 3, seg = idx & 7;
                const __nv_bfloat16* src =
                    (tile == 0) ? Khi  + (size_t)(kbase + r) * DD + seg * 8 :
                    (tile == 1) ? Klo  + (size_t)(kbase + r) * DD + seg * 8 :
                    (tile == 2) ? Vthi + (size_t)r * SS + kbase + seg * 8 :
                                  Vtlo + (size_t)r * SS + kbase + seg * 8;
                cp_async16(sb + tile * FT + r * 144 + seg * 16, src);
            }
            cp_commit();
            asm volatile("cp.async.wait_group 1;" ::: "memory");
        } else {
            asm volatile("cp.async.wait_group 0;" ::: "memory");
        }
        __syncthreads();

        uint32_t sb = sbase + (c & 1) * FBUF;

        #pragma unroll
        for (int j = 0; j < 8; j++) { s[j][0] = s[j][1] = s[j][2] = s[j][3] = 0.f; }
        #pragma unroll
        for (int kb = 0; kb < 4; kb++) {
            uint32_t kh[4][4], kl[4][4];
            #pragma unroll
            for (int j = 0; j < 4; j++)
                ldsm_x4(kh[j], sb + ((j * 16 + brow) * 72 + kb * 16 + bcg * 8) * 2);
            #pragma unroll
            for (int j = 0; j < 8; j++)
                mma16816(s[j], aqh[kb], kh[j >> 1][(j & 1) * 2], kh[j >> 1][(j & 1) * 2 + 1]);
            #pragma unroll
            for (int j = 0; j < 4; j++)
                ldsm_x4(kl[j], sb + FT + ((j * 16 + brow) * 72 + kb * 16 + bcg * 8) * 2);
            #pragma unroll
            for (int j = 0; j < 8; j++)
                mma16816(s[j], aqh[kb], kl[j >> 1][(j & 1) * 2], kl[j >> 1][(j & 1) * 2 + 1]);
            #pragma unroll
            for (int j = 0; j < 8; j++)
                mma16816(s[j], aql[kb], kh[j >> 1][(j & 1) * 2], kh[j >> 1][(j & 1) * 2 + 1]);
        }

        float mx0 = s[0][0], mx1 = s[0][2];
        #pragma unroll
        for (int j = 0; j < 8; j++) {
            mx0 = fmaxf(mx0, fmaxf(s[j][0], s[j][1]));
            mx1 = fmaxf(mx1, fmaxf(s[j][2], s[j][3]));
        }
        mx0 = fmaxf(mx0, __shfl_xor_sync(0xffffffffu, mx0, 1));
        mx0 = fmaxf(mx0, __shfl_xor_sync(0xffffffffu, mx0, 2));
        mx1 = fmaxf(mx1, __shfl_xor_sync(0xffffffffu, mx1, 1));
        mx1 = fmaxf(mx1, __shfl_xor_sync(0xffffffffu, mx1, 2));
        float mn0 = fmaxf(m0, mx0), mn1 = fmaxf(m1, mx1);
        float al0 = __expf(m0 - mn0), al1 = __expf(m1 - mn1);
        m0 = mn0; m1 = mn1;
        float sum0 = 0.f, sum1 = 0.f;
        #pragma unroll
        for (int j = 0; j < 8; j++) {
            s[j][0] = __expf(s[j][0] - mn0);
            s[j][1] = __expf(s[j][1] - mn0);
            s[j][2] = __expf(s[j][2] - mn1);
            s[j][3] = __expf(s[j][3] - mn1);
            sum0 += s[j][0] + s[j][1];
            sum1 += s[j][2] + s[j][3];
        }
        sum0 += __shfl_xor_sync(0xffffffffu, sum0, 1);
        sum0 += __shfl_xor_sync(0xffffffffu, sum0, 2);
        sum1 += __shfl_xor_sync(0xffffffffu, sum1, 1);
        sum1 += __shfl_xor_sync(0xffffffffu, sum1, 2);
        l0 = l0 * al0 + sum0;
        l1 = l1 * al1 + sum1;
        #pragma unroll
        for (int j = 0; j < 8; j++) {
            o[j][0] *= al0; o[j][1] *= al0; o[j][2] *= al1; o[j][3] *= al1;
        }

        #pragma unroll
        for (int kb = 0; kb < 4; kb++) {
            float e0 = s[2 * kb][0],     e1 = s[2 * kb][1];
            float e2 = s[2 * kb][2],     e3 = s[2 * kb][3];
            float e4 = s[2 * kb + 1][0], e5 = s[2 * kb + 1][1];
            float e6 = s[2 * kb + 1][2], e7 = s[2 * kb + 1][3];
            uint32_t ph[4], pl[4];
            ph[0] = pack_bf(e0, e1);  ph[1] = pack_bf(e2, e3);
            ph[2] = pack_bf(e4, e5);  ph[3] = pack_bf(e6, e7);
            pl[0] = pack_bf(e0 - bf16f(e0), e1 - bf16f(e1));
            pl[1] = pack_bf(e2 - bf16f(e2), e3 - bf16f(e3));
            pl[2] = pack_bf(e4 - bf16f(e4), e5 - bf16f(e5));
            pl[3] = pack_bf(e6 - bf16f(e6), e7 - bf16f(e7));

            uint32_t vh[4][4], vl[4][4];
            #pragma unroll
            for (int j = 0; j < 4; j++)
                ldsm_x4(vh[j], sb + 2 * FT + ((j * 16 + brow) * 72 + kb * 16 + bcg * 8) * 2);
            #pragma unroll
            for (int j = 0; j < 8; j++)
                mma16816(o[j], ph, vh[j >> 1][(j & 1) * 2], vh[j >> 1][(j & 1) * 2 + 1]);
            #pragma unroll
            for (int j = 0; j < 4; j++)
                ldsm_x4(vl[j], sb + 3 * FT + ((j * 16 + brow) * 72 + kb * 16 + bcg * 8) * 2);
            #pragma unroll
            for (int j = 0; j < 8; j++)
                mma16816(o[j], ph, vl[j >> 1][(j & 1) * 2], vl[j >> 1][(j & 1) * 2 + 1]);
            #pragma unroll
            for (int j = 0; j < 8; j++)
                mma16816(o[j], pl, vh[j >> 1][(j & 1) * 2], vh[j >> 1][(j & 1) * 2 + 1]);
        }
        __syncthreads();
    }

    float i0 = 1.f / l0, i1 = 1.f / l1;
    int r0 = qt * 128 + w * 16 + (lane >> 2);
    #pragma unroll
    for (int j = 0; j < 8; j++) {
        int n = h * 64 + j * 8 + (lane & 3) * 2;
        size_t o0 = ((size_t)(b * SS) + r0) * HID + n;
        size_t o1 = o0 + 8 * HID;
        float a0 = o[j][0] * i0, a1 = o[j][1] * i0;
        float a2 = o[j][2] * i1, a3 = o[j][3] * i1;
        *(uint32_t*)&g_ahi[o0] = pack_bf(a0, a1);
        *(uint32_t*)&g_alo[o0] = pack_bf(a0 - bf16f(a0), a1 - bf16f(a1));
        *(uint32_t*)&g_ahi[o1] = pack_bf(a2, a3);
        *(uint32_t*)&g_alo[o1] = pack_bf(a2 - bf16f(a2), a3 - bf16f(a3));
    }
}

// ==================== launch ====================
extern "C" void kernel_launch(void* const* d_in, const int* in_sizes, int n_in,
                              void* d_out, int out_size)
{
    const float* x  = (const float*)d_in[0];
    const float* Wq = (const float*)d_in[1];
    const float* Wk = (const float*)d_in[2];
    const float* Wv = (const float*)d_in[3];
    const float* Wo = (const float*)d_in[4];
    const float* W1 = (const float*)d_in[5];
    const float* b1 = (const float*)d_in[6];
    const float* W2 = (const float*)d_in[7];
    const float* b2 = (const float*)d_in[8];
    float* out = (float*)d_out;

    cudaFuncSetAttribute(mm_mma_kernel<0>, cudaFuncAttributeMaxDynamicSharedMemorySize, SMEM_MM);
    cudaFuncSetAttribute(mm_mma_kernel<1>, cudaFuncAttributeMaxDynamicSharedMemorySize, SMEM_MM);
    cudaFuncSetAttribute(flash_mma_kernel, cudaFuncAttributeMaxDynamicSharedMemorySize, SMEM_F);

    repo_mlp_kernel<<<512, 128>>>(x, W1, b1, W2, b2);
    scan_kernel<<<2, 1024>>>();
    angles_kernel<<<512, 256>>>();
    conv_split_kernel<<<4096, 256>>>(x);
    conv_wT_kernel<<<dim3(32, 32, 4), dim3(32, 32)>>>(Wq, Wk, Wv, Wo);
    mm_mma_kernel<0><<<dim3(8, 32, 3), 256, SMEM_MM>>>(nullptr);
    flash_mma_kernel<<<dim3(16, 32), 256, SMEM_F>>>();
    mm_mma_kernel<1><<<dim3(8, 32, 1), 256, SMEM_MM>>>(out);
}